// round 1
// baseline (speedup 1.0000x reference)
#include <cuda_runtime.h>
#include <math.h>

#define B_ 4
#define T_ 2048
#define C_ 1024
#define H_ 128
#define E_ 16
#define N_ (B_*T_)   /* 8192 tokens */

// ---------------- scratch (allocation-free: __device__ globals) ----------------
__device__ float g_q[(size_t)N_*H_];
__device__ float g_k[(size_t)N_*H_];
__device__ float g_v[(size_t)N_*H_];
__device__ float g_o[(size_t)N_*H_];
__device__ float g_S[(size_t)B_*T_*T_];      // 67 MB attention scores
__device__ int   g_cnt[E_];
__device__ int   g_idx[(size_t)E_*N_];
__device__ float g_wt[(size_t)E_*N_];
__device__ float g_invsn[E_];
__device__ float g_sig[E_];

// ---------------- zero init (q,k,v accumulators, counters, output) -------------
__global__ void zero_all(float* __restrict__ out) {
    size_t i  = (size_t)blockIdx.x * blockDim.x + threadIdx.x;
    size_t st = (size_t)gridDim.x * blockDim.x;
    for (size_t j = i; j < (size_t)N_*H_; j += st) { g_q[j]=0.f; g_k[j]=0.f; g_v[j]=0.f; }
    for (size_t j = i; j < (size_t)N_*C_; j += st) out[j] = 0.f;
    if (i < E_) g_cnt[i] = 0;
}

// ---------------- sim-matrix column norms + sigmoid(gates) ---------------------
__global__ void prep_kernel(const float* __restrict__ sim, const float* __restrict__ gates) {
    int e = threadIdx.x >> 5, lane = threadIdx.x & 31;
    float s = 0.f;
    for (int c = lane; c < C_; c += 32) { float v = sim[(size_t)c*E_ + e]; s += v*v; }
    #pragma unroll
    for (int o = 16; o > 0; o >>= 1) s += __shfl_xor_sync(0xffffffffu, s, o);
    if (lane == 0) {
        g_invsn[e] = 1.0f / fmaxf(sqrtf(s), 1e-12f);
        g_sig[e]   = 1.0f / (1.0f + expf(-gates[e]));
    }
}

// ---------------- gating: logits, mask/STE/fallback, softmax, expert lists -----
// one warp per token
__global__ void gating_kernel(const float* __restrict__ x, const float* __restrict__ sim) {
    int tok  = blockIdx.x * (blockDim.x >> 5) + (threadIdx.x >> 5);
    int lane = threadIdx.x & 31;
    if (tok >= N_) return;
    const float* xr = x + (size_t)tok * C_;

    float dot[E_];
    #pragma unroll
    for (int e = 0; e < E_; e++) dot[e] = 0.f;
    float nrm = 0.f;
    for (int c = lane; c < C_; c += 32) {
        float xv = xr[c];
        nrm += xv * xv;
        const float4* s4 = (const float4*)(sim + (size_t)c * E_);
        float4 r0 = s4[0], r1 = s4[1], r2 = s4[2], r3 = s4[3];
        dot[0]+=xv*r0.x; dot[1]+=xv*r0.y; dot[2]+=xv*r0.z; dot[3]+=xv*r0.w;
        dot[4]+=xv*r1.x; dot[5]+=xv*r1.y; dot[6]+=xv*r1.z; dot[7]+=xv*r1.w;
        dot[8]+=xv*r2.x; dot[9]+=xv*r2.y; dot[10]+=xv*r2.z; dot[11]+=xv*r2.w;
        dot[12]+=xv*r3.x; dot[13]+=xv*r3.y; dot[14]+=xv*r3.z; dot[15]+=xv*r3.w;
    }
    #pragma unroll
    for (int o = 16; o > 0; o >>= 1) {
        nrm += __shfl_xor_sync(0xffffffffu, nrm, o);
        #pragma unroll
        for (int e = 0; e < E_; e++) dot[e] += __shfl_xor_sync(0xffffffffu, dot[e], o);
    }
    float invx = 1.0f / fmaxf(sqrtf(nrm), 1e-12f);

    float logit[E_], gated[E_];
    unsigned msk = 0u;
    #pragma unroll
    for (int e = 0; e < E_; e++) {
        logit[e] = dot[e] * invx * g_invsn[e] - g_sig[e];
        gated[e] = fmaxf(logit[e], 0.f);
        if (logit[e] > 0.f) msk |= (1u << e);
    }
    if (msk == 0u) {
        // fallback: top-2 logits (stable: first index wins ties, matches lax.top_k)
        float m1 = -3.4e38f; int i1 = 0;
        #pragma unroll
        for (int e = 0; e < E_; e++) if (logit[e] > m1) { m1 = logit[e]; i1 = e; }
        float m2 = -3.4e38f; int i2 = 0;
        #pragma unroll
        for (int e = 0; e < E_; e++) if (e != i1 && logit[e] > m2) { m2 = logit[e]; i2 = e; }
        msk = (1u << i1) | (1u << i2);
    }
    // softmax over masked gated values
    float mx = -3.4e38f;
    #pragma unroll
    for (int e = 0; e < E_; e++) if ((msk >> e) & 1u) mx = fmaxf(mx, gated[e]);
    float wv[E_]; float sum = 0.f;
    #pragma unroll
    for (int e = 0; e < E_; e++) {
        wv[e] = ((msk >> e) & 1u) ? expf(gated[e] - mx) : 0.f;
        sum += wv[e];
    }
    float inv = 1.0f / sum;
    // append to expert lists (lanes 0..15, one expert each)
    #pragma unroll
    for (int e = 0; e < E_; e++) {
        if (lane == e && ((msk >> e) & 1u)) {
            int pos = atomicAdd(&g_cnt[e], 1);
            g_idx[(size_t)e * N_ + pos] = tok;
            g_wt [(size_t)e * N_ + pos] = wv[e] * inv;
        }
    }
}

// ---------------- unified tiled GEMM ------------------------------------------
// C[m,n] (+)= alpha * rowscale[m] * sum_k A[gather(m),k] * B(k,n)
// TRANSB=0: B[k*ldb+n] ; TRANSB=1: B[n*ldb+k]
// Tiles: BM=64, BN=128, BK=16; 256 threads; per-thread 4x8 micro-tile.
template<bool TRANSB, bool GATHER, bool ATOMIC>
__global__ void __launch_bounds__(256)
gemm_k(const float* __restrict__ A, int lda, long strideAz,
       const float* __restrict__ B, int ldb, long strideBz,
       float* __restrict__ Cm, int ldc, long strideCz,
       int M, int K, float alpha,
       const int* __restrict__ cnt,
       const int* __restrict__ idxBase,
       const float* __restrict__ wtBase)
{
    int z = blockIdx.z;
    int Mz = M;
    const int*   gidx = nullptr;
    const float* gwt  = nullptr;
    if (GATHER) {
        Mz   = cnt[z];
        gidx = idxBase + (size_t)z * N_;
        gwt  = wtBase  + (size_t)z * N_;
    }
    int m0 = blockIdx.y * 64;
    if (m0 >= Mz) return;
    int n0 = blockIdx.x * 128;
    A += (size_t)z * strideAz;
    B += (size_t)z * strideBz;
    Cm += (size_t)z * strideCz;

    __shared__ float As[16][64];
    __shared__ float Bs[16][128];

    int tid = threadIdx.x;
    int ty = tid >> 4, tx = tid & 15;       // ty: 16 row-groups of 4, tx: 16 col-groups of 8

    float acc[4][8];
    #pragma unroll
    for (int i = 0; i < 4; i++)
        #pragma unroll
        for (int j = 0; j < 8; j++) acc[i][j] = 0.f;

    // A-load mapping: each thread one float4 along k
    int aRow = tid >> 2;
    int aK   = (tid & 3) << 2;
    bool aval = (m0 + aRow) < Mz;
    size_t aOff = 0;
    if (aval) {
        int r = m0 + aRow;
        int grow = GATHER ? gidx[r] : r;
        aOff = (size_t)grow * lda + aK;
    }

    for (int k0 = 0; k0 < K; k0 += 16) {
        float4 av = make_float4(0.f, 0.f, 0.f, 0.f);
        if (aval) av = *(const float4*)(A + aOff + k0);

        float4 bv0, bv1;
        int bK = 0, bN = 0, bNt = 0, bKq = 0;
        if (!TRANSB) {
            bK = tid >> 4; bN = (tid & 15) << 3;
            const float* bp = B + (size_t)(k0 + bK) * ldb + n0 + bN;
            bv0 = *(const float4*)bp;
            bv1 = *(const float4*)(bp + 4);
        } else {
            bNt = tid >> 1; bKq = (tid & 1) << 3;
            const float* bp = B + (size_t)(n0 + bNt) * ldb + k0 + bKq;
            bv0 = *(const float4*)bp;
            bv1 = *(const float4*)(bp + 4);
        }

        __syncthreads();
        As[aK+0][aRow] = av.x; As[aK+1][aRow] = av.y;
        As[aK+2][aRow] = av.z; As[aK+3][aRow] = av.w;
        if (!TRANSB) {
            *(float4*)&Bs[bK][bN]     = bv0;
            *(float4*)&Bs[bK][bN + 4] = bv1;
        } else {
            Bs[bKq+0][bNt]=bv0.x; Bs[bKq+1][bNt]=bv0.y; Bs[bKq+2][bNt]=bv0.z; Bs[bKq+3][bNt]=bv0.w;
            Bs[bKq+4][bNt]=bv1.x; Bs[bKq+5][bNt]=bv1.y; Bs[bKq+6][bNt]=bv1.z; Bs[bKq+7][bNt]=bv1.w;
        }
        __syncthreads();

        #pragma unroll
        for (int kk = 0; kk < 16; kk++) {
            float a[4], b[8];
            *(float4*)a       = *(float4*)&As[kk][ty << 2];
            *(float4*)b       = *(float4*)&Bs[kk][tx << 3];
            *(float4*)(b + 4) = *(float4*)&Bs[kk][(tx << 3) + 4];
            #pragma unroll
            for (int i = 0; i < 4; i++)
                #pragma unroll
                for (int j = 0; j < 8; j++)
                    acc[i][j] += a[i] * b[j];
        }
    }

    #pragma unroll
    for (int i = 0; i < 4; i++) {
        int r = m0 + (ty << 2) + i;
        if (r < Mz) {
            float sc = alpha;
            int orow = r;
            if (GATHER) { sc *= gwt[r]; orow = gidx[r]; }
            float* cp = Cm + (size_t)orow * ldc + n0 + (tx << 3);
            #pragma unroll
            for (int j = 0; j < 8; j++) {
                float vvv = acc[i][j] * sc;
                if (ATOMIC) atomicAdd(cp + j, vvv);
                else        cp[j] = vvv;
            }
        }
    }
}

// ---------------- row softmax over S (row length T_) ---------------------------
__global__ void softmax_kernel() {
    __shared__ float buf[T_];
    __shared__ float red[256];
    float* S = g_S + (size_t)blockIdx.x * T_;
    int tid = threadIdx.x;
    float mx = -3.4e38f;
    for (int j = tid; j < T_; j += 256) { float v = S[j]; buf[j] = v; mx = fmaxf(mx, v); }
    red[tid] = mx; __syncthreads();
    for (int s = 128; s > 0; s >>= 1) { if (tid < s) red[tid] = fmaxf(red[tid], red[tid+s]); __syncthreads(); }
    mx = red[0];
    __syncthreads();
    float sum = 0.f;
    for (int j = tid; j < T_; j += 256) { float e = __expf(buf[j] - mx); buf[j] = e; sum += e; }
    red[tid] = sum; __syncthreads();
    for (int s = 128; s > 0; s >>= 1) { if (tid < s) red[tid] += red[tid+s]; __syncthreads(); }
    float inv = 1.0f / red[0];
    for (int j = tid; j < T_; j += 256) S[j] = buf[j] * inv;
}

// ---------------- launch ---------------------------------------------------------
extern "C" void kernel_launch(void* const* d_in, const int* in_sizes, int n_in,
                              void* d_out, int out_size)
{
    const float* x     = (const float*)d_in[0];
    const float* sim   = (const float*)d_in[1];
    const float* gates = (const float*)d_in[2];
    const float* qp    = (const float*)d_in[3];
    const float* kp    = (const float*)d_in[4];
    const float* vp    = (const float*)d_in[5];
    const float* op    = (const float*)d_in[6];
    float* outp = (float*)d_out;

    float *q, *k, *v, *o, *S, *wt;
    int *cnt, *idx;
    cudaGetSymbolAddress((void**)&q,   g_q);
    cudaGetSymbolAddress((void**)&k,   g_k);
    cudaGetSymbolAddress((void**)&v,   g_v);
    cudaGetSymbolAddress((void**)&o,   g_o);
    cudaGetSymbolAddress((void**)&S,   g_S);
    cudaGetSymbolAddress((void**)&cnt, g_cnt);
    cudaGetSymbolAddress((void**)&idx, g_idx);
    cudaGetSymbolAddress((void**)&wt,  g_wt);

    zero_all<<<2048, 256>>>(outp);
    prep_kernel<<<1, 512>>>(sim, gates);
    gating_kernel<<<N_/8, 256>>>(x, sim);

    // MoE dispatch: q/k/v = sum_e w[:,e] * (X @ P_e)   (gathered, atomic-accum)
    dim3 gqkv(1, N_/64, E_);
    gemm_k<false, true, true><<<gqkv, 256>>>(x, C_, 0, qp, H_, (long)C_*H_,
                                             q, H_, 0, 0, C_, 1.f, cnt, idx, wt);
    gemm_k<false, true, true><<<gqkv, 256>>>(x, C_, 0, kp, H_, (long)C_*H_,
                                             k, H_, 0, 0, C_, 1.f, cnt, idx, wt);
    gemm_k<false, true, true><<<gqkv, 256>>>(x, C_, 0, vp, H_, (long)C_*H_,
                                             v, H_, 0, 0, C_, 1.f, cnt, idx, wt);

    // S = QK^T / sqrt(H)
    dim3 gqk(T_/128, T_/64, B_);
    gemm_k<true, false, false><<<gqk, 256>>>(q, H_, (long)T_*H_, k, H_, (long)T_*H_,
                                             S, T_, (long)T_*T_, T_, H_,
                                             0.08838834764831845f, nullptr, nullptr, nullptr);

    softmax_kernel<<<B_*T_, 256>>>();

    // O = P @ V
    dim3 gpv(H_/128, T_/64, B_);
    gemm_k<false, false, false><<<gpv, 256>>>(S, T_, (long)T_*T_, v, H_, (long)T_*H_,
                                              o, H_, (long)T_*H_, T_, T_,
                                              1.f, nullptr, nullptr, nullptr);

    // MoE combine: out = sum_e w[:,e] * (O @ Oproj_e)   (gathered, atomic-accum)
    dim3 gout(C_/128, N_/64, E_);
    gemm_k<false, true, true><<<gout, 256>>>(o, H_, 0, op, C_, (long)H_*C_,
                                             outp, C_, 0, 0, H_, 1.f, cnt, idx, wt);
}

// round 8
// speedup vs baseline: 2.9112x; 2.9112x over previous
#include <cuda_runtime.h>
#include <cuda_bf16.h>
#include <math.h>
#include <stdint.h>

#define B_ 4
#define T_ 2048
#define C_ 1024
#define H_ 128
#define E_ 16
#define N_ (B_*T_)   /* 8192 tokens */

using bf16  = __nv_bfloat16;
using bf162 = __nv_bfloat162;

// ---------------- scratch (allocation-free: __device__ globals) ----------------
__device__ float g_q[(size_t)N_*H_];
__device__ float g_k[(size_t)N_*H_];
__device__ float g_v[(size_t)N_*H_];
__device__ float g_o[(size_t)N_*H_];
__device__ float g_S[(size_t)B_*T_*T_];          // 64 MB f32 scores

__device__ bf16 g_xh[(size_t)N_*C_],  g_xl[(size_t)N_*C_];
__device__ bf16 g_qh[(size_t)N_*H_],  g_ql[(size_t)N_*H_];
__device__ bf16 g_kh[(size_t)N_*H_],  g_kl[(size_t)N_*H_];
__device__ bf16 g_vTh[(size_t)N_*H_], g_vTl[(size_t)N_*H_];   // [B][H][T]
__device__ bf16 g_oh[(size_t)N_*H_],  g_ol[(size_t)N_*H_];
__device__ bf16 g_Sh[(size_t)B_*T_*T_], g_Sl[(size_t)B_*T_*T_];
__device__ bf16 g_wqh[(size_t)E_*H_*C_], g_wql[(size_t)E_*H_*C_];  // [E][H][C]
__device__ bf16 g_wkh[(size_t)E_*H_*C_], g_wkl[(size_t)E_*H_*C_];
__device__ bf16 g_wvh[(size_t)E_*H_*C_], g_wvl[(size_t)E_*H_*C_];
__device__ bf16 g_woh[(size_t)E_*C_*H_], g_wol[(size_t)E_*C_*H_];  // [E][C][H]

__device__ int   g_cnt[E_];
__device__ int   g_idx[(size_t)E_*N_];
__device__ float g_wt[(size_t)E_*N_];
__device__ float g_invsn[E_];
__device__ float g_sig[E_];

// ---------------- mma.sync helper (baseline PTX, valid on compute_103) ----------
#define MMA16816(d, A0, A1, A2, A3, Bv0, Bv1) \
    asm volatile("mma.sync.aligned.m16n8k16.row.col.f32.bf16.bf16.f32 " \
        "{%0,%1,%2,%3},{%4,%5,%6,%7},{%8,%9},{%0,%1,%2,%3};" \
        : "+f"((d)[0]), "+f"((d)[1]), "+f"((d)[2]), "+f"((d)[3]) \
        : "r"(A0), "r"(A1), "r"(A2), "r"(A3), "r"(Bv0), "r"(Bv1))

// ---------------- HMMA GEMM -----------------------------------------------------
// D[m][n] = alpha * (w[m]) * sum_k A[m][k]*B[n][k]   (A,B split hi/lo bf16, K-major)
struct TCArgs {
    const bf16 *Ah, *Al;
    const bf16 *Bh0, *Bl0, *Bh1, *Bl1, *Bh2, *Bl2;
    float *C0, *C1, *C2;
    long sAz, sBz, sCz;
    int  lda, ldb, ldc;
    int  M, K, nxb, nsplit, ksplit;
    float alpha;
    const int* cnt; const int* idxB; const float* wtB;
};

#define PITCH 20   /* row pitch in b32 units: 16 b32 (32 bf16) + 4 pad */

template<bool GATHER, bool ATOMIC>
__global__ void __launch_bounds__(256, 2) hm_gemm(TCArgs a)
{
    int zb  = blockIdx.z / a.nsplit;
    int sp  = blockIdx.z % a.nsplit;
    int mat = blockIdx.x / a.nxb;
    int n0  = (blockIdx.x % a.nxb) * 128;

    int Mz = a.M;
    const int*   gidx = nullptr;
    const float* gwt  = nullptr;
    if (GATHER) {
        Mz   = a.cnt[zb];
        gidx = a.idxB + (size_t)zb * N_;
        gwt  = a.wtB  + (size_t)zb * N_;
    }
    int m0 = blockIdx.y * 128;
    if (m0 >= Mz) return;

    const bf16* Ah = a.Ah + (size_t)zb * a.sAz;
    const bf16* Al = a.Al + (size_t)zb * a.sAz;
    const bf16* Bh = (mat == 0 ? a.Bh0 : mat == 1 ? a.Bh1 : a.Bh2) + (size_t)zb * a.sBz;
    const bf16* Bl = (mat == 0 ? a.Bl0 : mat == 1 ? a.Bl1 : a.Bl2) + (size_t)zb * a.sBz;
    float*      C  = (mat == 0 ? a.C0  : mat == 1 ? a.C1  : a.C2)  + (size_t)zb * a.sCz;

    __shared__ uint32_t sAh[128*PITCH], sAl[128*PITCH];
    __shared__ uint32_t sBh[128*PITCH], sBl[128*PITCH];
    __shared__ int      s_idx[128];
    __shared__ float    s_wt[128];

    int tid  = threadIdx.x;
    int lane = tid & 31, wid = tid >> 5;
    int g = lane >> 2, t = lane & 3;
    int wm = wid & 1, wn = wid >> 1;          // warp grid 2 (m) x 4 (n)
    int mbw = wm * 64, nbw = wn * 32;

    if (GATHER) {
        for (int i = tid; i < 128; i += 256) {
            int r = m0 + i;
            bool v = r < Mz;
            s_idx[i] = v ? gidx[r] : 0;
            s_wt[i]  = v ? gwt[r] : 0.f;
        }
    }
    __syncthreads();

    float acc[4][4][4];
    #pragma unroll
    for (int i = 0; i < 4; i++)
        #pragma unroll
        for (int j = 0; j < 4; j++)
            #pragma unroll
            for (int c = 0; c < 4; c++) acc[i][j][c] = 0.f;

    int kb = sp * a.ksplit;
    int ke = kb + a.ksplit; if (ke > a.K) ke = a.K;

    // per-thread load coordinates (fixed across k-chunks)
    int f0row = tid >> 2,          f0kq = tid & 3;
    int f1row = (tid + 256) >> 2,  f1kq = (tid + 256) & 3;
    long ar0 = GATHER ? (long)s_idx[f0row] : (long)(m0 + f0row);
    long ar1 = GATHER ? (long)s_idx[f1row] : (long)(m0 + f1row);
    long br0 = (long)(n0 + f0row), br1 = (long)(n0 + f1row);
    int so0 = f0row * PITCH + f0kq * 4;
    int so1 = f1row * PITCH + f1kq * 4;

    for (int k0 = kb; k0 < ke; k0 += 32) {
        // issue global loads BEFORE the barrier that closes the previous phase
        uint4 vAh0 = *(const uint4*)(Ah + ar0 * (long)a.lda + k0 + f0kq * 8);
        uint4 vAl0 = *(const uint4*)(Al + ar0 * (long)a.lda + k0 + f0kq * 8);
        uint4 vBh0 = *(const uint4*)(Bh + br0 * (long)a.ldb + k0 + f0kq * 8);
        uint4 vBl0 = *(const uint4*)(Bl + br0 * (long)a.ldb + k0 + f0kq * 8);
        uint4 vAh1 = *(const uint4*)(Ah + ar1 * (long)a.lda + k0 + f1kq * 8);
        uint4 vAl1 = *(const uint4*)(Al + ar1 * (long)a.lda + k0 + f1kq * 8);
        uint4 vBh1 = *(const uint4*)(Bh + br1 * (long)a.ldb + k0 + f1kq * 8);
        uint4 vBl1 = *(const uint4*)(Bl + br1 * (long)a.ldb + k0 + f1kq * 8);

        if (k0 > kb) __syncthreads();
        *(uint4*)&sAh[so0] = vAh0;  *(uint4*)&sAl[so0] = vAl0;
        *(uint4*)&sBh[so0] = vBh0;  *(uint4*)&sBl[so0] = vBl0;
        *(uint4*)&sAh[so1] = vAh1;  *(uint4*)&sAl[so1] = vAl1;
        *(uint4*)&sBh[so1] = vBh1;  *(uint4*)&sBl[so1] = vBl1;
        __syncthreads();

        #pragma unroll
        for (int kk = 0; kk < 2; kk++) {
            int ko = kk * 8 + t;
            uint32_t bh[4][2], bl[4][2];
            #pragma unroll
            for (int nt = 0; nt < 4; nt++) {
                int nr = (nbw + nt * 8 + g) * PITCH + ko;
                bh[nt][0] = sBh[nr]; bh[nt][1] = sBh[nr + 4];
                bl[nt][0] = sBl[nr]; bl[nt][1] = sBl[nr + 4];
            }
            #pragma unroll
            for (int mt = 0; mt < 4; mt++) {
                int r0 = (mbw + mt * 16 + g) * PITCH + ko;
                int r1 = r0 + 8 * PITCH;
                uint32_t ah0 = sAh[r0], ah1 = sAh[r1], ah2 = sAh[r0 + 4], ah3 = sAh[r1 + 4];
                uint32_t al0 = sAl[r0], al1 = sAl[r1], al2 = sAl[r0 + 4], al3 = sAl[r1 + 4];
                #pragma unroll
                for (int nt = 0; nt < 4; nt++) {
                    MMA16816(acc[mt][nt], ah0, ah1, ah2, ah3, bh[nt][0], bh[nt][1]);
                    MMA16816(acc[mt][nt], ah0, ah1, ah2, ah3, bl[nt][0], bl[nt][1]);
                    MMA16816(acc[mt][nt], al0, al1, al2, al3, bh[nt][0], bh[nt][1]);
                }
            }
        }
    }

    // epilogue: c0,c1 -> row (g), cols 2t,2t+1 ; c2,c3 -> row (g+8)
    #pragma unroll
    for (int mt = 0; mt < 4; mt++) {
        #pragma unroll
        for (int half = 0; half < 2; half++) {
            int lr = mbw + mt * 16 + g + half * 8;
            bool rv; long orow; float sc;
            if (GATHER) { rv = (m0 + lr) < Mz; orow = s_idx[lr]; sc = a.alpha * s_wt[lr]; }
            else        { rv = true;           orow = m0 + lr;   sc = a.alpha; }
            if (rv) {
                float* cp = C + orow * (long)a.ldc + n0 + nbw;
                #pragma unroll
                for (int nt = 0; nt < 4; nt++) {
                    int col = nt * 8 + 2 * t;
                    float v0 = acc[mt][nt][half * 2 + 0] * sc;
                    float v1 = acc[mt][nt][half * 2 + 1] * sc;
                    if (ATOMIC) { atomicAdd(cp + col, v0); atomicAdd(cp + col + 1, v1); }
                    else        { float2 vv; vv.x = v0; vv.y = v1; *(float2*)(cp + col) = vv; }
                }
            }
        }
    }
}

// ---------------- zero init ------------------------------------------------------
__global__ void zero_all(float* __restrict__ out) {
    size_t i  = (size_t)blockIdx.x * blockDim.x + threadIdx.x;
    size_t st = (size_t)gridDim.x * blockDim.x;
    for (size_t j = i; j < (size_t)N_*H_; j += st) { g_q[j]=0.f; g_k[j]=0.f; g_v[j]=0.f; g_o[j]=0.f; }
    for (size_t j = i; j < (size_t)N_*C_; j += st) out[j] = 0.f;
    if (i < E_) g_cnt[i] = 0;
}

// ---------------- sim-matrix column norms + sigmoid(gates) -----------------------
__global__ void prep_kernel(const float* __restrict__ sim, const float* __restrict__ gates) {
    int e = threadIdx.x >> 5, lane = threadIdx.x & 31;
    float s = 0.f;
    for (int c = lane; c < C_; c += 32) { float v = sim[(size_t)c*E_ + e]; s += v*v; }
    #pragma unroll
    for (int o = 16; o > 0; o >>= 1) s += __shfl_xor_sync(0xffffffffu, s, o);
    if (lane == 0) {
        g_invsn[e] = 1.0f / fmaxf(sqrtf(s), 1e-12f);
        g_sig[e]   = 1.0f / (1.0f + expf(-gates[e]));
    }
}

// ---------------- gating (one warp per token) ------------------------------------
__global__ void gating_kernel(const float* __restrict__ x, const float* __restrict__ sim) {
    int tok  = blockIdx.x * (blockDim.x >> 5) + (threadIdx.x >> 5);
    int lane = threadIdx.x & 31;
    if (tok >= N_) return;
    const float* xr = x + (size_t)tok * C_;

    float dot[E_];
    #pragma unroll
    for (int e = 0; e < E_; e++) dot[e] = 0.f;
    float nrm = 0.f;
    for (int c = lane; c < C_; c += 32) {
        float xv = xr[c];
        nrm += xv * xv;
        const float4* s4 = (const float4*)(sim + (size_t)c * E_);
        float4 r0 = s4[0], r1 = s4[1], r2 = s4[2], r3 = s4[3];
        dot[0]+=xv*r0.x; dot[1]+=xv*r0.y; dot[2]+=xv*r0.z; dot[3]+=xv*r0.w;
        dot[4]+=xv*r1.x; dot[5]+=xv*r1.y; dot[6]+=xv*r1.z; dot[7]+=xv*r1.w;
        dot[8]+=xv*r2.x; dot[9]+=xv*r2.y; dot[10]+=xv*r2.z; dot[11]+=xv*r2.w;
        dot[12]+=xv*r3.x; dot[13]+=xv*r3.y; dot[14]+=xv*r3.z; dot[15]+=xv*r3.w;
    }
    #pragma unroll
    for (int o = 16; o > 0; o >>= 1) {
        nrm += __shfl_xor_sync(0xffffffffu, nrm, o);
        #pragma unroll
        for (int e = 0; e < E_; e++) dot[e] += __shfl_xor_sync(0xffffffffu, dot[e], o);
    }
    float invx = 1.0f / fmaxf(sqrtf(nrm), 1e-12f);

    float logit[E_], gated[E_];
    unsigned msk = 0u;
    #pragma unroll
    for (int e = 0; e < E_; e++) {
        logit[e] = dot[e] * invx * g_invsn[e] - g_sig[e];
        gated[e] = fmaxf(logit[e], 0.f);
        if (logit[e] > 0.f) msk |= (1u << e);
    }
    if (msk == 0u) {
        float m1 = -3.4e38f; int i1 = 0;
        #pragma unroll
        for (int e = 0; e < E_; e++) if (logit[e] > m1) { m1 = logit[e]; i1 = e; }
        float m2 = -3.4e38f; int i2 = 0;
        #pragma unroll
        for (int e = 0; e < E_; e++) if (e != i1 && logit[e] > m2) { m2 = logit[e]; i2 = e; }
        msk = (1u << i1) | (1u << i2);
    }
    float mx = -3.4e38f;
    #pragma unroll
    for (int e = 0; e < E_; e++) if ((msk >> e) & 1u) mx = fmaxf(mx, gated[e]);
    float wv[E_]; float sum = 0.f;
    #pragma unroll
    for (int e = 0; e < E_; e++) {
        wv[e] = ((msk >> e) & 1u) ? expf(gated[e] - mx) : 0.f;
        sum += wv[e];
    }
    float inv = 1.0f / sum;
    #pragma unroll
    for (int e = 0; e < E_; e++) {
        if (lane == e && ((msk >> e) & 1u)) {
            int pos = atomicAdd(&g_cnt[e], 1);
            g_idx[(size_t)e * N_ + pos] = tok;
            g_wt [(size_t)e * N_ + pos] = wv[e] * inv;
        }
    }
}

// ---------------- f32 -> bf16 hi/lo split (vectorized) ---------------------------
__global__ void split2(const float* __restrict__ in, bf16* __restrict__ hi,
                       bf16* __restrict__ lo, long n4)
{
    long i  = (long)blockIdx.x * blockDim.x + threadIdx.x;
    long st = (long)gridDim.x * blockDim.x;
    for (; i < n4; i += st) {
        float4 v = ((const float4*)in)[i];
        bf16 h0 = __float2bfloat16(v.x), h1 = __float2bfloat16(v.y);
        bf16 h2 = __float2bfloat16(v.z), h3 = __float2bfloat16(v.w);
        bf162 hh0; hh0.x = h0; hh0.y = h1;
        bf162 hh1; hh1.x = h2; hh1.y = h3;
        ((bf162*)hi)[2*i]   = hh0;
        ((bf162*)hi)[2*i+1] = hh1;
        bf162 ll0, ll1;
        ll0.x = __float2bfloat16(v.x - __bfloat162float(h0));
        ll0.y = __float2bfloat16(v.y - __bfloat162float(h1));
        ll1.x = __float2bfloat16(v.z - __bfloat162float(h2));
        ll1.y = __float2bfloat16(v.w - __bfloat162float(h3));
        ((bf162*)lo)[2*i]   = ll0;
        ((bf162*)lo)[2*i+1] = ll1;
    }
}

// ---------------- transpose + split: out[c][r] = in[r][c] ------------------------
__global__ void tsplit(const float* __restrict__ in, bf16* __restrict__ oh,
                       bf16* __restrict__ ol, int R, int Cc)
{
    __shared__ float t[32][33];
    size_t zo = (size_t)blockIdx.z * R * Cc;
    in += zo; oh += zo; ol += zo;
    int c0 = blockIdx.x * 32, r0 = blockIdx.y * 32;
    int tx = threadIdx.x, ty = threadIdx.y;
    #pragma unroll
    for (int i = ty; i < 32; i += 8) t[i][tx] = in[(size_t)(r0 + i) * Cc + c0 + tx];
    __syncthreads();
    #pragma unroll
    for (int i = ty; i < 32; i += 8) {
        float v = t[tx][i];
        bf16 h = __float2bfloat16(v);
        size_t oidx = (size_t)(c0 + i) * R + r0 + tx;
        oh[oidx] = h;
        ol[oidx] = __float2bfloat16(v - __bfloat162float(h));
    }
}

// ---------------- softmax over S rows, writing bf16 hi/lo ------------------------
__global__ void softmax_split() {
    __shared__ float buf[T_];
    __shared__ float red[256];
    const float* S = g_S + (size_t)blockIdx.x * T_;
    bf16* sh = g_Sh + (size_t)blockIdx.x * T_;
    bf16* sl = g_Sl + (size_t)blockIdx.x * T_;
    int tid = threadIdx.x;
    float mx = -3.4e38f;
    for (int j = tid; j < T_; j += 256) { float v = S[j]; buf[j] = v; mx = fmaxf(mx, v); }
    red[tid] = mx; __syncthreads();
    for (int s = 128; s > 0; s >>= 1) { if (tid < s) red[tid] = fmaxf(red[tid], red[tid+s]); __syncthreads(); }
    mx = red[0];
    __syncthreads();
    float sum = 0.f;
    for (int j = tid; j < T_; j += 256) { float e = __expf(buf[j] - mx); buf[j] = e; sum += e; }
    red[tid] = sum; __syncthreads();
    for (int s = 128; s > 0; s >>= 1) { if (tid < s) red[tid] += red[tid+s]; __syncthreads(); }
    float inv = 1.0f / red[0];
    for (int j = tid; j < T_; j += 256) {
        float p = buf[j] * inv;
        bf16 h = __float2bfloat16(p);
        sh[j] = h;
        sl[j] = __float2bfloat16(p - __bfloat162float(h));
    }
}

// ---------------- launch ---------------------------------------------------------
extern "C" void kernel_launch(void* const* d_in, const int* in_sizes, int n_in,
                              void* d_out, int out_size)
{
    const float* x     = (const float*)d_in[0];
    const float* sim   = (const float*)d_in[1];
    const float* gates = (const float*)d_in[2];
    const float* qp    = (const float*)d_in[3];
    const float* kp    = (const float*)d_in[4];
    const float* vp    = (const float*)d_in[5];
    const float* op    = (const float*)d_in[6];
    float* outp = (float*)d_out;

    float *q, *k, *v, *o, *S, *wt;
    int *cnt, *idx;
    bf16 *xh, *xl, *qh, *ql, *kh, *kl, *vTh, *vTl, *oh, *ol, *Sh, *Sl;
    bf16 *wqh, *wql, *wkh, *wkl, *wvh, *wvl, *woh, *wol;
    cudaGetSymbolAddress((void**)&q, g_q);     cudaGetSymbolAddress((void**)&k, g_k);
    cudaGetSymbolAddress((void**)&v, g_v);     cudaGetSymbolAddress((void**)&o, g_o);
    cudaGetSymbolAddress((void**)&S, g_S);
    cudaGetSymbolAddress((void**)&cnt, g_cnt); cudaGetSymbolAddress((void**)&idx, g_idx);
    cudaGetSymbolAddress((void**)&wt, g_wt);
    cudaGetSymbolAddress((void**)&xh, g_xh);   cudaGetSymbolAddress((void**)&xl, g_xl);
    cudaGetSymbolAddress((void**)&qh, g_qh);   cudaGetSymbolAddress((void**)&ql, g_ql);
    cudaGetSymbolAddress((void**)&kh, g_kh);   cudaGetSymbolAddress((void**)&kl, g_kl);
    cudaGetSymbolAddress((void**)&vTh, g_vTh); cudaGetSymbolAddress((void**)&vTl, g_vTl);
    cudaGetSymbolAddress((void**)&oh, g_oh);   cudaGetSymbolAddress((void**)&ol, g_ol);
    cudaGetSymbolAddress((void**)&Sh, g_Sh);   cudaGetSymbolAddress((void**)&Sl, g_Sl);
    cudaGetSymbolAddress((void**)&wqh, g_wqh); cudaGetSymbolAddress((void**)&wql, g_wql);
    cudaGetSymbolAddress((void**)&wkh, g_wkh); cudaGetSymbolAddress((void**)&wkl, g_wkl);
    cudaGetSymbolAddress((void**)&wvh, g_wvh); cudaGetSymbolAddress((void**)&wvl, g_wvl);
    cudaGetSymbolAddress((void**)&woh, g_woh); cudaGetSymbolAddress((void**)&wol, g_wol);

    zero_all<<<2048, 256>>>(outp);
    prep_kernel<<<1, 512>>>(sim, gates);
    gating_kernel<<<N_/8, 256>>>(x, sim);

    // pre-split / pre-transpose operands to bf16 hi/lo
    split2<<<2048, 256>>>(x, xh, xl, (long)N_*C_/4);
    tsplit<<<dim3(H_/32, C_/32, E_), dim3(32,8)>>>(qp, wqh, wql, C_, H_);   // [E][C][H]->[E][H][C]
    tsplit<<<dim3(H_/32, C_/32, E_), dim3(32,8)>>>(kp, wkh, wkl, C_, H_);
    tsplit<<<dim3(H_/32, C_/32, E_), dim3(32,8)>>>(vp, wvh, wvl, C_, H_);
    tsplit<<<dim3(C_/32, H_/32, E_), dim3(32,8)>>>(op, woh, wol, H_, C_);   // [E][H][C]->[E][C][H]

    // QKV MoE dispatch (gathered rows, weighted atomic accumulate into q/k/v f32)
    {
        TCArgs a{};
        a.Ah = xh; a.Al = xl;
        a.Bh0 = wqh; a.Bl0 = wql; a.Bh1 = wkh; a.Bl1 = wkl; a.Bh2 = wvh; a.Bl2 = wvl;
        a.C0 = q; a.C1 = k; a.C2 = v;
        a.sAz = 0; a.sBz = (long)H_*C_; a.sCz = 0;
        a.lda = C_; a.ldb = C_; a.ldc = H_;
        a.M = N_; a.K = C_; a.nxb = 1; a.nsplit = 1; a.ksplit = C_;
        a.alpha = 1.f; a.cnt = cnt; a.idxB = idx; a.wtB = wt;
        hm_gemm<true, true><<<dim3(3, 64, 16), 256>>>(a);
    }

    split2<<<512, 256>>>(q, qh, ql, (long)N_*H_/4);
    split2<<<512, 256>>>(k, kh, kl, (long)N_*H_/4);
    tsplit<<<dim3(H_/32, T_/32, B_), dim3(32,8)>>>(v, vTh, vTl, T_, H_);    // [T][H]->[H][T] per batch

    // S = Q K^T / sqrt(H)
    {
        TCArgs a{};
        a.Ah = qh; a.Al = ql;
        a.Bh0 = kh; a.Bl0 = kl; a.Bh1 = kh; a.Bl1 = kl; a.Bh2 = kh; a.Bl2 = kl;
        a.C0 = S; a.C1 = S; a.C2 = S;
        a.sAz = (long)T_*H_; a.sBz = (long)T_*H_; a.sCz = (long)T_*T_;
        a.lda = H_; a.ldb = H_; a.ldc = T_;
        a.M = T_; a.K = H_; a.nxb = 16; a.nsplit = 1; a.ksplit = H_;
        a.alpha = 0.08838834764831845f;
        hm_gemm<false, false><<<dim3(16, 16, 4), 256>>>(a);
    }

    softmax_split<<<B_*T_, 256>>>();

    // O = P V   (split-K x4, atomic accumulate into o f32)
    {
        TCArgs a{};
        a.Ah = Sh; a.Al = Sl;
        a.Bh0 = vTh; a.Bl0 = vTl; a.Bh1 = vTh; a.Bl1 = vTl; a.Bh2 = vTh; a.Bl2 = vTl;
        a.C0 = o; a.C1 = o; a.C2 = o;
        a.sAz = (long)T_*T_; a.sBz = (long)H_*T_; a.sCz = (long)T_*H_;
        a.lda = T_; a.ldb = T_; a.ldc = H_;
        a.M = T_; a.K = T_; a.nxb = 1; a.nsplit = 4; a.ksplit = 512;
        a.alpha = 1.f;
        hm_gemm<false, true><<<dim3(1, 16, 16), 256>>>(a);
    }

    split2<<<512, 256>>>(o, oh, ol, (long)N_*H_/4);

    // output MoE combine (gathered rows, weighted atomic accumulate into out)
    {
        TCArgs a{};
        a.Ah = oh; a.Al = ol;
        a.Bh0 = woh; a.Bl0 = wol; a.Bh1 = woh; a.Bl1 = wol; a.Bh2 = woh; a.Bl2 = wol;
        a.C0 = outp; a.C1 = outp; a.C2 = outp;
        a.sAz = 0; a.sBz = (long)C_*H_; a.sCz = 0;
        a.lda = H_; a.ldb = H_; a.ldc = C_;
        a.M = N_; a.K = H_; a.nxb = 8; a.nsplit = 1; a.ksplit = H_;
        a.alpha = 1.f; a.cnt = cnt; a.idxB = idx; a.wtB = wt;
        hm_gemm<true, true><<<dim3(8, 64, 16), 256>>>(a);
    }
}

// round 9
// speedup vs baseline: 3.0819x; 1.0586x over previous
#include <cuda_runtime.h>
#include <cuda_bf16.h>
#include <math.h>
#include <stdint.h>

#define B_ 4
#define T_ 2048
#define C_ 1024
#define H_ 128
#define E_ 16
#define N_ (B_*T_)   /* 8192 tokens */

using bf16  = __nv_bfloat16;
using bf162 = __nv_bfloat162;

// ---------------- scratch (allocation-free: __device__ globals) ----------------
__device__ float g_q[(size_t)N_*H_];
__device__ float g_k[(size_t)N_*H_];
__device__ float g_v[(size_t)N_*H_];
__device__ float g_o[(size_t)N_*H_];
__device__ float g_S[(size_t)B_*T_*T_];          // 64 MB f32 scores

__device__ bf16 g_xh[(size_t)N_*C_],  g_xl[(size_t)N_*C_];
__device__ bf16 g_qh[(size_t)N_*H_],  g_ql[(size_t)N_*H_];
__device__ bf16 g_kh[(size_t)N_*H_],  g_kl[(size_t)N_*H_];
__device__ bf16 g_vTh[(size_t)N_*H_], g_vTl[(size_t)N_*H_];   // [B][H][T]
__device__ bf16 g_oh[(size_t)N_*H_],  g_ol[(size_t)N_*H_];
__device__ bf16 g_Sh[(size_t)B_*T_*T_], g_Sl[(size_t)B_*T_*T_];
__device__ bf16 g_wqh[(size_t)E_*H_*C_], g_wql[(size_t)E_*H_*C_];  // [E][H][C]
__device__ bf16 g_wkh[(size_t)E_*H_*C_], g_wkl[(size_t)E_*H_*C_];
__device__ bf16 g_wvh[(size_t)E_*H_*C_], g_wvl[(size_t)E_*H_*C_];
__device__ bf16 g_woh[(size_t)E_*C_*H_], g_wol[(size_t)E_*C_*H_];  // [E][C][H]

__device__ int   g_cnt[E_];
__device__ int   g_idx[(size_t)E_*N_];
__device__ float g_wt[(size_t)E_*N_];
__device__ float g_invsn[E_];
__device__ float g_sig[E_];

// ---------------- mma.sync + ldmatrix helpers (baseline PTX) --------------------
#define MMA16816(d, A0, A1, A2, A3, Bv0, Bv1) \
    asm volatile("mma.sync.aligned.m16n8k16.row.col.f32.bf16.bf16.f32 " \
        "{%0,%1,%2,%3},{%4,%5,%6,%7},{%8,%9},{%0,%1,%2,%3};" \
        : "+f"((d)[0]), "+f"((d)[1]), "+f"((d)[2]), "+f"((d)[3]) \
        : "r"(A0), "r"(A1), "r"(A2), "r"(A3), "r"(Bv0), "r"(Bv1))

#define LDSM4(r0, r1, r2, r3, addr) \
    asm volatile("ldmatrix.sync.aligned.m8n8.x4.shared.b16 {%0,%1,%2,%3}, [%4];" \
        : "=r"(r0), "=r"(r1), "=r"(r2), "=r"(r3) : "r"(addr))

__device__ __forceinline__ uint32_t smem_u32(const void* p) {
    uint32_t a;
    asm("{ .reg .u64 t; cvta.to.shared.u64 t, %1; cvt.u32.u64 %0, t; }" : "=r"(a) : "l"(p));
    return a;
}

// ---------------- HMMA GEMM -----------------------------------------------------
// D[m][n] = alpha * (w[m]) * sum_k A[m][k]*B[n][k]   (A,B split hi/lo bf16, K-major)
struct TCArgs {
    const bf16 *Ah, *Al;
    const bf16 *Bh0, *Bl0, *Bh1, *Bl1, *Bh2, *Bl2;
    float *C0, *C1, *C2;
    long sAz, sBz, sCz;
    int  lda, ldb, ldc;
    int  M, K, nxb, nsplit, ksplit;
    float alpha;
    const int* cnt; const int* idxB; const float* wtB;
};

#define PITCH 20   /* row pitch in b32 units: 16 b32 (32 bf16) + 4 pad */

template<bool GATHER, bool ATOMIC>
__global__ void __launch_bounds__(256, 2) hm_gemm(TCArgs a)
{
    int zb  = blockIdx.z / a.nsplit;
    int sp  = blockIdx.z % a.nsplit;
    int mat = blockIdx.x / a.nxb;
    int n0  = (blockIdx.x % a.nxb) * 128;

    int Mz = a.M;
    const int*   gidx = nullptr;
    const float* gwt  = nullptr;
    if (GATHER) {
        Mz   = a.cnt[zb];
        gidx = a.idxB + (size_t)zb * N_;
        gwt  = a.wtB  + (size_t)zb * N_;
    }
    int m0 = blockIdx.y * 128;
    if (m0 >= Mz) return;

    const bf16* Ah = a.Ah + (size_t)zb * a.sAz;
    const bf16* Al = a.Al + (size_t)zb * a.sAz;
    const bf16* Bh = (mat == 0 ? a.Bh0 : mat == 1 ? a.Bh1 : a.Bh2) + (size_t)zb * a.sBz;
    const bf16* Bl = (mat == 0 ? a.Bl0 : mat == 1 ? a.Bl1 : a.Bl2) + (size_t)zb * a.sBz;
    float*      C  = (mat == 0 ? a.C0  : mat == 1 ? a.C1  : a.C2)  + (size_t)zb * a.sCz;

    __shared__ uint32_t sAh[128*PITCH], sAl[128*PITCH];
    __shared__ uint32_t sBh[128*PITCH], sBl[128*PITCH];
    __shared__ int      s_idx[128];
    __shared__ float    s_wt[128];

    int tid  = threadIdx.x;
    int lane = tid & 31, wid = tid >> 5;
    int g = lane >> 2, t = lane & 3;
    int wm = wid & 1, wn = wid >> 1;          // warp grid 2 (m) x 4 (n)
    int mbw = wm * 64, nbw = wn * 32;

    if (GATHER) {
        for (int i = tid; i < 128; i += 256) {
            int r = m0 + i;
            bool v = r < Mz;
            s_idx[i] = v ? gidx[r] : 0;
            s_wt[i]  = v ? gwt[r] : 0.f;
        }
    }
    __syncthreads();

    float acc[4][4][4];
    #pragma unroll
    for (int i = 0; i < 4; i++)
        #pragma unroll
        for (int j = 0; j < 4; j++)
            #pragma unroll
            for (int c = 0; c < 4; c++) acc[i][j][c] = 0.f;

    int kb = sp * a.ksplit;
    int ke = kb + a.ksplit; if (ke > a.K) ke = a.K;

    // per-thread global load coordinates (fixed across k-chunks)
    int f0row = tid >> 2,          f0kq = tid & 3;
    int f1row = (tid + 256) >> 2,  f1kq = (tid + 256) & 3;
    long ar0 = GATHER ? (long)s_idx[f0row] : (long)(m0 + f0row);
    long ar1 = GATHER ? (long)s_idx[f1row] : (long)(m0 + f1row);
    long br0 = (long)(n0 + f0row), br1 = (long)(n0 + f1row);
    int so0 = f0row * PITCH + f0kq * 4;
    int so1 = f1row * PITCH + f1kq * 4;

    // ldmatrix lane-address offsets (bytes)
    int jj = lane >> 3, rr = lane & 7;
    uint32_t aoff = (uint32_t)(((jj & 1) * 8 + rr) * PITCH + (jj >> 1) * 4) * 4u;
    uint32_t boff = (uint32_t)(((jj >> 1) * 8 + rr) * PITCH + (jj & 1) * 4) * 4u;
    uint32_t baseAh = smem_u32(sAh) + (uint32_t)(mbw * PITCH) * 4u + aoff;
    uint32_t baseAl = smem_u32(sAl) + (uint32_t)(mbw * PITCH) * 4u + aoff;
    uint32_t baseBh = smem_u32(sBh) + (uint32_t)(nbw * PITCH) * 4u + boff;
    uint32_t baseBl = smem_u32(sBl) + (uint32_t)(nbw * PITCH) * 4u + boff;

    for (int k0 = kb; k0 < ke; k0 += 32) {
        // issue global loads BEFORE the barrier that closes the previous phase
        uint4 vAh0 = *(const uint4*)(Ah + ar0 * (long)a.lda + k0 + f0kq * 8);
        uint4 vAl0 = *(const uint4*)(Al + ar0 * (long)a.lda + k0 + f0kq * 8);
        uint4 vBh0 = *(const uint4*)(Bh + br0 * (long)a.ldb + k0 + f0kq * 8);
        uint4 vBl0 = *(const uint4*)(Bl + br0 * (long)a.ldb + k0 + f0kq * 8);
        uint4 vAh1 = *(const uint4*)(Ah + ar1 * (long)a.lda + k0 + f1kq * 8);
        uint4 vAl1 = *(const uint4*)(Al + ar1 * (long)a.lda + k0 + f1kq * 8);
        uint4 vBh1 = *(const uint4*)(Bh + br1 * (long)a.ldb + k0 + f1kq * 8);
        uint4 vBl1 = *(const uint4*)(Bl + br1 * (long)a.ldb + k0 + f1kq * 8);

        if (k0 > kb) __syncthreads();
        *(uint4*)&sAh[so0] = vAh0;  *(uint4*)&sAl[so0] = vAl0;
        *(uint4*)&sBh[so0] = vBh0;  *(uint4*)&sBl[so0] = vBl0;
        *(uint4*)&sAh[so1] = vAh1;  *(uint4*)&sAl[so1] = vAl1;
        *(uint4*)&sBh[so1] = vBh1;  *(uint4*)&sBl[so1] = vBl1;
        __syncthreads();

        #pragma unroll
        for (int kk = 0; kk < 2; kk++) {
            uint32_t kadd = (uint32_t)(kk * 8) * 4u;
            // B fragments: 2 ldmatrix.x4 per h/l cover all 4 n8-tiles
            uint32_t bh[4][2], bl[4][2];
            #pragma unroll
            for (int np = 0; np < 2; np++) {
                uint32_t ba = (uint32_t)(np * 16 * PITCH) * 4u + kadd;
                LDSM4(bh[2*np][0], bh[2*np][1], bh[2*np+1][0], bh[2*np+1][1], baseBh + ba);
                LDSM4(bl[2*np][0], bl[2*np][1], bl[2*np+1][0], bl[2*np+1][1], baseBl + ba);
            }
            #pragma unroll
            for (int mt = 0; mt < 4; mt++) {
                uint32_t ma = (uint32_t)(mt * 16 * PITCH) * 4u + kadd;
                uint32_t ah0, ah1, ah2, ah3, al0, al1, al2, al3;
                LDSM4(ah0, ah1, ah2, ah3, baseAh + ma);
                LDSM4(al0, al1, al2, al3, baseAl + ma);
                #pragma unroll
                for (int nt = 0; nt < 4; nt++) {
                    MMA16816(acc[mt][nt], ah0, ah1, ah2, ah3, bh[nt][0], bh[nt][1]);
                    MMA16816(acc[mt][nt], ah0, ah1, ah2, ah3, bl[nt][0], bl[nt][1]);
                    MMA16816(acc[mt][nt], al0, al1, al2, al3, bh[nt][0], bh[nt][1]);
                }
            }
        }
    }

    // epilogue: c0,c1 -> row (g), cols 2t,2t+1 ; c2,c3 -> row (g+8)
    #pragma unroll
    for (int mt = 0; mt < 4; mt++) {
        #pragma unroll
        for (int half = 0; half < 2; half++) {
            int lr = mbw + mt * 16 + g + half * 8;
            bool rv; long orow; float sc;
            if (GATHER) { rv = (m0 + lr) < Mz; orow = s_idx[lr]; sc = a.alpha * s_wt[lr]; }
            else        { rv = true;           orow = m0 + lr;   sc = a.alpha; }
            if (rv) {
                float* cp = C + orow * (long)a.ldc + n0 + nbw;
                #pragma unroll
                for (int nt = 0; nt < 4; nt++) {
                    int col = nt * 8 + 2 * t;
                    float v0 = acc[mt][nt][half * 2 + 0] * sc;
                    float v1 = acc[mt][nt][half * 2 + 1] * sc;
                    if (ATOMIC) { atomicAdd(cp + col, v0); atomicAdd(cp + col + 1, v1); }
                    else        { float2 vv; vv.x = v0; vv.y = v1; *(float2*)(cp + col) = vv; }
                }
            }
        }
    }
}

// ---------------- zero init ------------------------------------------------------
__global__ void zero_all(float* __restrict__ out) {
    size_t i  = (size_t)blockIdx.x * blockDim.x + threadIdx.x;
    size_t st = (size_t)gridDim.x * blockDim.x;
    for (size_t j = i; j < (size_t)N_*H_; j += st) { g_q[j]=0.f; g_k[j]=0.f; g_v[j]=0.f; g_o[j]=0.f; }
    for (size_t j = i; j < (size_t)N_*C_; j += st) out[j] = 0.f;
    if (i < E_) g_cnt[i] = 0;
}

// ---------------- sim-matrix column norms + sigmoid(gates) -----------------------
__global__ void prep_kernel(const float* __restrict__ sim, const float* __restrict__ gates) {
    int e = threadIdx.x >> 5, lane = threadIdx.x & 31;
    float s = 0.f;
    for (int c = lane; c < C_; c += 32) { float v = sim[(size_t)c*E_ + e]; s += v*v; }
    #pragma unroll
    for (int o = 16; o > 0; o >>= 1) s += __shfl_xor_sync(0xffffffffu, s, o);
    if (lane == 0) {
        g_invsn[e] = 1.0f / fmaxf(sqrtf(s), 1e-12f);
        g_sig[e]   = 1.0f / (1.0f + expf(-gates[e]));
    }
}

// ---------------- gating (one warp per token) ------------------------------------
__global__ void gating_kernel(const float* __restrict__ x, const float* __restrict__ sim) {
    int tok  = blockIdx.x * (blockDim.x >> 5) + (threadIdx.x >> 5);
    int lane = threadIdx.x & 31;
    if (tok >= N_) return;
    const float* xr = x + (size_t)tok * C_;

    float dot[E_];
    #pragma unroll
    for (int e = 0; e < E_; e++) dot[e] = 0.f;
    float nrm = 0.f;
    for (int c = lane; c < C_; c += 32) {
        float xv = xr[c];
        nrm += xv * xv;
        const float4* s4 = (const float4*)(sim + (size_t)c * E_);
        float4 r0 = s4[0], r1 = s4[1], r2 = s4[2], r3 = s4[3];
        dot[0]+=xv*r0.x; dot[1]+=xv*r0.y; dot[2]+=xv*r0.z; dot[3]+=xv*r0.w;
        dot[4]+=xv*r1.x; dot[5]+=xv*r1.y; dot[6]+=xv*r1.z; dot[7]+=xv*r1.w;
        dot[8]+=xv*r2.x; dot[9]+=xv*r2.y; dot[10]+=xv*r2.z; dot[11]+=xv*r2.w;
        dot[12]+=xv*r3.x; dot[13]+=xv*r3.y; dot[14]+=xv*r3.z; dot[15]+=xv*r3.w;
    }
    #pragma unroll
    for (int o = 16; o > 0; o >>= 1) {
        nrm += __shfl_xor_sync(0xffffffffu, nrm, o);
        #pragma unroll
        for (int e = 0; e < E_; e++) dot[e] += __shfl_xor_sync(0xffffffffu, dot[e], o);
    }
    float invx = 1.0f / fmaxf(sqrtf(nrm), 1e-12f);

    float logit[E_], gated[E_];
    unsigned msk = 0u;
    #pragma unroll
    for (int e = 0; e < E_; e++) {
        logit[e] = dot[e] * invx * g_invsn[e] - g_sig[e];
        gated[e] = fmaxf(logit[e], 0.f);
        if (logit[e] > 0.f) msk |= (1u << e);
    }
    if (msk == 0u) {
        float m1 = -3.4e38f; int i1 = 0;
        #pragma unroll
        for (int e = 0; e < E_; e++) if (logit[e] > m1) { m1 = logit[e]; i1 = e; }
        float m2 = -3.4e38f; int i2 = 0;
        #pragma unroll
        for (int e = 0; e < E_; e++) if (e != i1 && logit[e] > m2) { m2 = logit[e]; i2 = e; }
        msk = (1u << i1) | (1u << i2);
    }
    float mx = -3.4e38f;
    #pragma unroll
    for (int e = 0; e < E_; e++) if ((msk >> e) & 1u) mx = fmaxf(mx, gated[e]);
    float wv[E_]; float sum = 0.f;
    #pragma unroll
    for (int e = 0; e < E_; e++) {
        wv[e] = ((msk >> e) & 1u) ? expf(gated[e] - mx) : 0.f;
        sum += wv[e];
    }
    float inv = 1.0f / sum;
    #pragma unroll
    for (int e = 0; e < E_; e++) {
        if (lane == e && ((msk >> e) & 1u)) {
            int pos = atomicAdd(&g_cnt[e], 1);
            g_idx[(size_t)e * N_ + pos] = tok;
            g_wt [(size_t)e * N_ + pos] = wv[e] * inv;
        }
    }
}

// ---------------- f32 -> bf16 hi/lo split (vectorized) ---------------------------
__global__ void split2(const float* __restrict__ in, bf16* __restrict__ hi,
                       bf16* __restrict__ lo, long n4)
{
    long i  = (long)blockIdx.x * blockDim.x + threadIdx.x;
    long st = (long)gridDim.x * blockDim.x;
    for (; i < n4; i += st) {
        float4 v = ((const float4*)in)[i];
        bf16 h0 = __float2bfloat16(v.x), h1 = __float2bfloat16(v.y);
        bf16 h2 = __float2bfloat16(v.z), h3 = __float2bfloat16(v.w);
        bf162 hh0; hh0.x = h0; hh0.y = h1;
        bf162 hh1; hh1.x = h2; hh1.y = h3;
        ((bf162*)hi)[2*i]   = hh0;
        ((bf162*)hi)[2*i+1] = hh1;
        bf162 ll0, ll1;
        ll0.x = __float2bfloat16(v.x - __bfloat162float(h0));
        ll0.y = __float2bfloat16(v.y - __bfloat162float(h1));
        ll1.x = __float2bfloat16(v.z - __bfloat162float(h2));
        ll1.y = __float2bfloat16(v.w - __bfloat162float(h3));
        ((bf162*)lo)[2*i]   = ll0;
        ((bf162*)lo)[2*i+1] = ll1;
    }
}

// ---------------- transpose + split: out[c][r] = in[r][c] ------------------------
__global__ void tsplit(const float* __restrict__ in, bf16* __restrict__ oh,
                       bf16* __restrict__ ol, int R, int Cc)
{
    __shared__ float t[32][33];
    size_t zo = (size_t)blockIdx.z * R * Cc;
    in += zo; oh += zo; ol += zo;
    int c0 = blockIdx.x * 32, r0 = blockIdx.y * 32;
    int tx = threadIdx.x, ty = threadIdx.y;
    #pragma unroll
    for (int i = ty; i < 32; i += 8) t[i][tx] = in[(size_t)(r0 + i) * Cc + c0 + tx];
    __syncthreads();
    #pragma unroll
    for (int i = ty; i < 32; i += 8) {
        float v = t[tx][i];
        bf16 h = __float2bfloat16(v);
        size_t oidx = (size_t)(c0 + i) * R + r0 + tx;
        oh[oidx] = h;
        ol[oidx] = __float2bfloat16(v - __bfloat162float(h));
    }
}

// ---------------- softmax over S rows, writing bf16 hi/lo ------------------------
__global__ void softmax_split() {
    __shared__ float buf[T_];
    __shared__ float red[256];
    const float* S = g_S + (size_t)blockIdx.x * T_;
    bf16* sh = g_Sh + (size_t)blockIdx.x * T_;
    bf16* sl = g_Sl + (size_t)blockIdx.x * T_;
    int tid = threadIdx.x;
    float mx = -3.4e38f;
    for (int j = tid; j < T_; j += 256) { float v = S[j]; buf[j] = v; mx = fmaxf(mx, v); }
    red[tid] = mx; __syncthreads();
    for (int s = 128; s > 0; s >>= 1) { if (tid < s) red[tid] = fmaxf(red[tid], red[tid+s]); __syncthreads(); }
    mx = red[0];
    __syncthreads();
    float sum = 0.f;
    for (int j = tid; j < T_; j += 256) { float e = __expf(buf[j] - mx); buf[j] = e; sum += e; }
    red[tid] = sum; __syncthreads();
    for (int s = 128; s > 0; s >>= 1) { if (tid < s) red[tid] += red[tid+s]; __syncthreads(); }
    float inv = 1.0f / red[0];
    for (int j = tid; j < T_; j += 256) {
        float p = buf[j] * inv;
        bf16 h = __float2bfloat16(p);
        sh[j] = h;
        sl[j] = __float2bfloat16(p - __bfloat162float(h));
    }
}

// ---------------- launch ---------------------------------------------------------
extern "C" void kernel_launch(void* const* d_in, const int* in_sizes, int n_in,
                              void* d_out, int out_size)
{
    const float* x     = (const float*)d_in[0];
    const float* sim   = (const float*)d_in[1];
    const float* gates = (const float*)d_in[2];
    const float* qp    = (const float*)d_in[3];
    const float* kp    = (const float*)d_in[4];
    const float* vp    = (const float*)d_in[5];
    const float* op    = (const float*)d_in[6];
    float* outp = (float*)d_out;

    float *q, *k, *v, *o, *S, *wt;
    int *cnt, *idx;
    bf16 *xh, *xl, *qh, *ql, *kh, *kl, *vTh, *vTl, *oh, *ol, *Sh, *Sl;
    bf16 *wqh, *wql, *wkh, *wkl, *wvh, *wvl, *woh, *wol;
    cudaGetSymbolAddress((void**)&q, g_q);     cudaGetSymbolAddress((void**)&k, g_k);
    cudaGetSymbolAddress((void**)&v, g_v);     cudaGetSymbolAddress((void**)&o, g_o);
    cudaGetSymbolAddress((void**)&S, g_S);
    cudaGetSymbolAddress((void**)&cnt, g_cnt); cudaGetSymbolAddress((void**)&idx, g_idx);
    cudaGetSymbolAddress((void**)&wt, g_wt);
    cudaGetSymbolAddress((void**)&xh, g_xh);   cudaGetSymbolAddress((void**)&xl, g_xl);
    cudaGetSymbolAddress((void**)&qh, g_qh);   cudaGetSymbolAddress((void**)&ql, g_ql);
    cudaGetSymbolAddress((void**)&kh, g_kh);   cudaGetSymbolAddress((void**)&kl, g_kl);
    cudaGetSymbolAddress((void**)&vTh, g_vTh); cudaGetSymbolAddress((void**)&vTl, g_vTl);
    cudaGetSymbolAddress((void**)&oh, g_oh);   cudaGetSymbolAddress((void**)&ol, g_ol);
    cudaGetSymbolAddress((void**)&Sh, g_Sh);   cudaGetSymbolAddress((void**)&Sl, g_Sl);
    cudaGetSymbolAddress((void**)&wqh, g_wqh); cudaGetSymbolAddress((void**)&wql, g_wql);
    cudaGetSymbolAddress((void**)&wkh, g_wkh); cudaGetSymbolAddress((void**)&wkl, g_wkl);
    cudaGetSymbolAddress((void**)&wvh, g_wvh); cudaGetSymbolAddress((void**)&wvl, g_wvl);
    cudaGetSymbolAddress((void**)&woh, g_woh); cudaGetSymbolAddress((void**)&wol, g_wol);

    zero_all<<<2048, 256>>>(outp);
    prep_kernel<<<1, 512>>>(sim, gates);
    gating_kernel<<<N_/8, 256>>>(x, sim);

    // pre-split / pre-transpose operands to bf16 hi/lo
    split2<<<2048, 256>>>(x, xh, xl, (long)N_*C_/4);
    tsplit<<<dim3(H_/32, C_/32, E_), dim3(32,8)>>>(qp, wqh, wql, C_, H_);   // [E][C][H]->[E][H][C]
    tsplit<<<dim3(H_/32, C_/32, E_), dim3(32,8)>>>(kp, wkh, wkl, C_, H_);
    tsplit<<<dim3(H_/32, C_/32, E_), dim3(32,8)>>>(vp, wvh, wvl, C_, H_);
    tsplit<<<dim3(C_/32, H_/32, E_), dim3(32,8)>>>(op, woh, wol, H_, C_);   // [E][H][C]->[E][C][H]

    // QKV MoE dispatch (gathered rows, weighted atomic accumulate into q/k/v f32)
    {
        TCArgs a{};
        a.Ah = xh; a.Al = xl;
        a.Bh0 = wqh; a.Bl0 = wql; a.Bh1 = wkh; a.Bl1 = wkl; a.Bh2 = wvh; a.Bl2 = wvl;
        a.C0 = q; a.C1 = k; a.C2 = v;
        a.sAz = 0; a.sBz = (long)H_*C_; a.sCz = 0;
        a.lda = C_; a.ldb = C_; a.ldc = H_;
        a.M = N_; a.K = C_; a.nxb = 1; a.nsplit = 1; a.ksplit = C_;
        a.alpha = 1.f; a.cnt = cnt; a.idxB = idx; a.wtB = wt;
        hm_gemm<true, true><<<dim3(3, 64, 16), 256>>>(a);
    }

    split2<<<512, 256>>>(q, qh, ql, (long)N_*H_/4);
    split2<<<512, 256>>>(k, kh, kl, (long)N_*H_/4);
    tsplit<<<dim3(H_/32, T_/32, B_), dim3(32,8)>>>(v, vTh, vTl, T_, H_);    // [T][H]->[H][T] per batch

    // S = Q K^T / sqrt(H)
    {
        TCArgs a{};
        a.Ah = qh; a.Al = ql;
        a.Bh0 = kh; a.Bl0 = kl; a.Bh1 = kh; a.Bl1 = kl; a.Bh2 = kh; a.Bl2 = kl;
        a.C0 = S; a.C1 = S; a.C2 = S;
        a.sAz = (long)T_*H_; a.sBz = (long)T_*H_; a.sCz = (long)T_*T_;
        a.lda = H_; a.ldb = H_; a.ldc = T_;
        a.M = T_; a.K = H_; a.nxb = 16; a.nsplit = 1; a.ksplit = H_;
        a.alpha = 0.08838834764831845f;
        hm_gemm<false, false><<<dim3(16, 16, 4), 256>>>(a);
    }

    softmax_split<<<B_*T_, 256>>>();

    // O = P V   (split-K x4, atomic accumulate into o f32)
    {
        TCArgs a{};
        a.Ah = Sh; a.Al = Sl;
        a.Bh0 = vTh; a.Bl0 = vTl; a.Bh1 = vTh; a.Bl1 = vTl; a.Bh2 = vTh; a.Bl2 = vTl;
        a.C0 = o; a.C1 = o; a.C2 = o;
        a.sAz = (long)T_*T_; a.sBz = (long)H_*T_; a.sCz = (long)T_*H_;
        a.lda = T_; a.ldb = T_; a.ldc = H_;
        a.M = T_; a.K = T_; a.nxb = 1; a.nsplit = 4; a.ksplit = 512;
        a.alpha = 1.f;
        hm_gemm<false, true><<<dim3(1, 16, 16), 256>>>(a);
    }

    split2<<<512, 256>>>(o, oh, ol, (long)N_*H_/4);

    // output MoE combine (gathered rows, weighted atomic accumulate into out)
    {
        TCArgs a{};
        a.Ah = oh; a.Al = ol;
        a.Bh0 = woh; a.Bl0 = wol; a.Bh1 = woh; a.Bl1 = wol; a.Bh2 = woh; a.Bl2 = wol;
        a.C0 = outp; a.C1 = outp; a.C2 = outp;
        a.sAz = 0; a.sBz = (long)C_*H_; a.sCz = 0;
        a.lda = H_; a.ldb = H_; a.ldc = C_;
        a.M = N_; a.K = H_; a.nxb = 8; a.nsplit = 1; a.ksplit = H_;
        a.alpha = 1.f; a.cnt = cnt; a.idxB = idx; a.wtB = wt;
        hm_gemm<true, true><<<dim3(8, 64, 16), 256>>>(a);
    }
}

// round 10
// speedup vs baseline: 3.3920x; 1.1006x over previous
#include <cuda_runtime.h>
#include <cuda_bf16.h>
#include <math.h>
#include <stdint.h>

#define B_ 4
#define T_ 2048
#define C_ 1024
#define H_ 128
#define E_ 16
#define N_ (B_*T_)   /* 8192 tokens */

using bf16  = __nv_bfloat16;
using bf162 = __nv_bfloat162;

// ---------------- scratch (allocation-free: __device__ globals) ----------------
__device__ float g_q[(size_t)N_*H_];
__device__ float g_k[(size_t)N_*H_];
__device__ float g_v[(size_t)N_*H_];
__device__ float g_o[(size_t)N_*H_];
__device__ float g_S[(size_t)B_*T_*T_];          // 64 MB f32 scores

__device__ bf16 g_xh[(size_t)N_*C_],  g_xl[(size_t)N_*C_];
__device__ bf16 g_qh[(size_t)N_*H_],  g_ql[(size_t)N_*H_];
__device__ bf16 g_kh[(size_t)N_*H_],  g_kl[(size_t)N_*H_];
__device__ bf16 g_vTh[(size_t)N_*H_], g_vTl[(size_t)N_*H_];   // [B][H][T]
__device__ bf16 g_oh[(size_t)N_*H_],  g_ol[(size_t)N_*H_];
__device__ bf16 g_Sh[(size_t)B_*T_*T_], g_Sl[(size_t)B_*T_*T_];
__device__ bf16 g_wqh[(size_t)E_*H_*C_], g_wql[(size_t)E_*H_*C_];  // [E][H][C]
__device__ bf16 g_wkh[(size_t)E_*H_*C_], g_wkl[(size_t)E_*H_*C_];
__device__ bf16 g_wvh[(size_t)E_*H_*C_], g_wvl[(size_t)E_*H_*C_];
__device__ bf16 g_woh[(size_t)E_*C_*H_], g_wol[(size_t)E_*C_*H_];  // [E][C][H]

__device__ int   g_cnt[E_];
__device__ int   g_idx[(size_t)E_*N_];
__device__ float g_wt[(size_t)E_*N_];
__device__ float g_invsn[E_];
__device__ float g_sig[E_];

// ---------------- mma.sync / ldmatrix / cp.async helpers (baseline PTX) ---------
#define MMA16816(d, A0, A1, A2, A3, Bv0, Bv1) \
    asm volatile("mma.sync.aligned.m16n8k16.row.col.f32.bf16.bf16.f32 " \
        "{%0,%1,%2,%3},{%4,%5,%6,%7},{%8,%9},{%0,%1,%2,%3};" \
        : "+f"((d)[0]), "+f"((d)[1]), "+f"((d)[2]), "+f"((d)[3]) \
        : "r"(A0), "r"(A1), "r"(A2), "r"(A3), "r"(Bv0), "r"(Bv1))

#define LDSM4(r0, r1, r2, r3, addr) \
    asm volatile("ldmatrix.sync.aligned.m8n8.x4.shared.b16 {%0,%1,%2,%3}, [%4];" \
        : "=r"(r0), "=r"(r1), "=r"(r2), "=r"(r3) : "r"(addr))

#define CPA16(dst, src) \
    asm volatile("cp.async.cg.shared.global [%0], [%1], 16;" :: "r"(dst), "l"(src))

__device__ __forceinline__ uint32_t smem_u32(const void* p) {
    uint32_t a;
    asm("{ .reg .u64 t; cvta.to.shared.u64 t, %1; cvt.u32.u64 %0, t; }" : "=r"(a) : "l"(p));
    return a;
}

// ---------------- HMMA GEMM -----------------------------------------------------
// D[m][n] = alpha * (w[m]) * sum_k A[m][k]*B[n][k]   (A,B split hi/lo bf16, K-major)
struct TCArgs {
    const bf16 *Ah, *Al;
    const bf16 *Bh0, *Bl0, *Bh1, *Bl1, *Bh2, *Bl2;
    float *C0, *C1, *C2;
    long sAz, sBz, sCz;
    int  lda, ldb, ldc;
    int  M, K, nxb, nsplit, ksplit;
    float alpha;
    const int* cnt; const int* idxB; const float* wtB;
};

#define PITCH 20   /* row pitch in b32 units: 16 b32 (32 bf16) + 4 pad */
#define TILE_U32 (128*PITCH)
#define DSM_BYTES (2*4*TILE_U32*4)   /* 2 buffers x 4 tiles = 81920 B */

template<bool GATHER, bool ATOMIC>
__global__ void __launch_bounds__(256, 2) hm_gemm(TCArgs a)
{
    int zb  = blockIdx.z / a.nsplit;
    int sp  = blockIdx.z % a.nsplit;
    int mat = blockIdx.x / a.nxb;
    int n0  = (blockIdx.x % a.nxb) * 128;

    int Mz = a.M;
    const int*   gidx = nullptr;
    const float* gwt  = nullptr;
    if (GATHER) {
        Mz   = a.cnt[zb];
        gidx = a.idxB + (size_t)zb * N_;
        gwt  = a.wtB  + (size_t)zb * N_;
    }
    int m0 = blockIdx.y * 128;
    if (m0 >= Mz) return;

    const bf16* Ah = a.Ah + (size_t)zb * a.sAz;
    const bf16* Al = a.Al + (size_t)zb * a.sAz;
    const bf16* Bh = (mat == 0 ? a.Bh0 : mat == 1 ? a.Bh1 : a.Bh2) + (size_t)zb * a.sBz;
    const bf16* Bl = (mat == 0 ? a.Bl0 : mat == 1 ? a.Bl1 : a.Bl2) + (size_t)zb * a.sBz;
    float*      C  = (mat == 0 ? a.C0  : mat == 1 ? a.C1  : a.C2)  + (size_t)zb * a.sCz;

    extern __shared__ uint32_t dsm[];
    uint32_t smbase = smem_u32(dsm);

    __shared__ int   s_idx[128];
    __shared__ float s_wt[128];

    int tid  = threadIdx.x;
    int lane = tid & 31, wid = tid >> 5;
    int g = lane >> 2, t = lane & 3;
    int wm = wid & 1, wn = wid >> 1;          // warp grid 2 (m) x 4 (n)
    int mbw = wm * 64, nbw = wn * 32;

    if (GATHER) {
        for (int i = tid; i < 128; i += 256) {
            int r = m0 + i;
            bool v = r < Mz;
            s_idx[i] = v ? gidx[r] : 0;
            s_wt[i]  = v ? gwt[r] : 0.f;
        }
    }
    __syncthreads();

    float acc[4][4][4];
    #pragma unroll
    for (int i = 0; i < 4; i++)
        #pragma unroll
        for (int j = 0; j < 4; j++)
            #pragma unroll
            for (int c = 0; c < 4; c++) acc[i][j][c] = 0.f;

    int kb = sp * a.ksplit;
    int ke = kb + a.ksplit; if (ke > a.K) ke = a.K;
    int nch = (ke - kb) >> 5;

    // per-thread global load coordinates (fixed across k-chunks)
    int f0row = tid >> 2,          f0kq = tid & 3;
    int f1row = (tid + 256) >> 2,  f1kq = (tid + 256) & 3;
    long ar0 = GATHER ? (long)s_idx[f0row] : (long)(m0 + f0row);
    long ar1 = GATHER ? (long)s_idx[f1row] : (long)(m0 + f1row);
    long br0 = (long)(n0 + f0row), br1 = (long)(n0 + f1row);
    uint32_t so0 = (uint32_t)(f0row * PITCH + f0kq * 4) * 4u;
    uint32_t so1 = (uint32_t)(f1row * PITCH + f1kq * 4) * 4u;

    // ldmatrix lane-address offsets (bytes)
    int jj = lane >> 3, rr = lane & 7;
    uint32_t aoff = (uint32_t)(((jj & 1) * 8 + rr) * PITCH + (jj >> 1) * 4) * 4u;
    uint32_t boff = (uint32_t)(((jj >> 1) * 8 + rr) * PITCH + (jj & 1) * 4) * 4u;
    uint32_t baseA = smbase + (uint32_t)(mbw * PITCH) * 4u + aoff;   // + tile offsets below
    uint32_t baseB = smbase + (uint32_t)(nbw * PITCH) * 4u + boff;
    const uint32_t TB = (uint32_t)TILE_U32 * 4u;   // tile stride in bytes

    // chunk loader: 8 cp.async of 16B into buffer b
    auto load_chunk = [&](int k0, int b) {
        uint32_t bb = (uint32_t)(b * 4) * TB;
        CPA16(smbase + bb + 0*TB + so0, Ah + ar0 * (long)a.lda + k0 + f0kq * 8);
        CPA16(smbase + bb + 1*TB + so0, Al + ar0 * (long)a.lda + k0 + f0kq * 8);
        CPA16(smbase + bb + 2*TB + so0, Bh + br0 * (long)a.ldb + k0 + f0kq * 8);
        CPA16(smbase + bb + 3*TB + so0, Bl + br0 * (long)a.ldb + k0 + f0kq * 8);
        CPA16(smbase + bb + 0*TB + so1, Ah + ar1 * (long)a.lda + k0 + f1kq * 8);
        CPA16(smbase + bb + 1*TB + so1, Al + ar1 * (long)a.lda + k0 + f1kq * 8);
        CPA16(smbase + bb + 2*TB + so1, Bh + br1 * (long)a.ldb + k0 + f1kq * 8);
        CPA16(smbase + bb + 3*TB + so1, Bl + br1 * (long)a.ldb + k0 + f1kq * 8);
    };

    load_chunk(kb, 0);
    asm volatile("cp.async.commit_group;" ::: "memory");

    for (int i = 0; i < nch; i++) {
        if (i + 1 < nch) {
            load_chunk(kb + (i + 1) * 32, (i + 1) & 1);
            asm volatile("cp.async.commit_group;" ::: "memory");
            asm volatile("cp.async.wait_group 1;" ::: "memory");
        } else {
            asm volatile("cp.async.wait_group 0;" ::: "memory");
        }
        __syncthreads();

        uint32_t bb = (uint32_t)((i & 1) * 4) * TB;
        uint32_t bAh = baseA + bb + 0*TB, bAl = baseA + bb + 1*TB;
        uint32_t bBh = baseB + bb + 2*TB, bBl = baseB + bb + 3*TB;

        #pragma unroll
        for (int kk = 0; kk < 2; kk++) {
            uint32_t kadd = (uint32_t)(kk * 8) * 4u;
            uint32_t bh[4][2], bl[4][2];
            #pragma unroll
            for (int np = 0; np < 2; np++) {
                uint32_t ba = (uint32_t)(np * 16 * PITCH) * 4u + kadd;
                LDSM4(bh[2*np][0], bh[2*np][1], bh[2*np+1][0], bh[2*np+1][1], bBh + ba);
                LDSM4(bl[2*np][0], bl[2*np][1], bl[2*np+1][0], bl[2*np+1][1], bBl + ba);
            }
            #pragma unroll
            for (int mt = 0; mt < 4; mt++) {
                uint32_t ma = (uint32_t)(mt * 16 * PITCH) * 4u + kadd;
                uint32_t ah0, ah1, ah2, ah3, al0, al1, al2, al3;
                LDSM4(ah0, ah1, ah2, ah3, bAh + ma);
                LDSM4(al0, al1, al2, al3, bAl + ma);
                #pragma unroll
                for (int nt = 0; nt < 4; nt++) {
                    MMA16816(acc[mt][nt], ah0, ah1, ah2, ah3, bh[nt][0], bh[nt][1]);
                    MMA16816(acc[mt][nt], ah0, ah1, ah2, ah3, bl[nt][0], bl[nt][1]);
                    MMA16816(acc[mt][nt], al0, al1, al2, al3, bh[nt][0], bh[nt][1]);
                }
            }
        }
        __syncthreads();
    }

    // epilogue: c0,c1 -> row (g), cols 2t,2t+1 ; c2,c3 -> row (g+8)
    #pragma unroll
    for (int mt = 0; mt < 4; mt++) {
        #pragma unroll
        for (int half = 0; half < 2; half++) {
            int lr = mbw + mt * 16 + g + half * 8;
            bool rv; long orow; float sc;
            if (GATHER) { rv = (m0 + lr) < Mz; orow = s_idx[lr]; sc = a.alpha * s_wt[lr]; }
            else        { rv = true;           orow = m0 + lr;   sc = a.alpha; }
            if (rv) {
                float* cp = C + orow * (long)a.ldc + n0 + nbw;
                #pragma unroll
                for (int nt = 0; nt < 4; nt++) {
                    int col = nt * 8 + 2 * t;
                    float v0 = acc[mt][nt][half * 2 + 0] * sc;
                    float v1 = acc[mt][nt][half * 2 + 1] * sc;
                    if (ATOMIC) { atomicAdd(cp + col, v0); atomicAdd(cp + col + 1, v1); }
                    else        { float2 vv; vv.x = v0; vv.y = v1; *(float2*)(cp + col) = vv; }
                }
            }
        }
    }
}

// ---------------- zero init ------------------------------------------------------
__global__ void zero_all(float* __restrict__ out) {
    size_t i  = (size_t)blockIdx.x * blockDim.x + threadIdx.x;
    size_t st = (size_t)gridDim.x * blockDim.x;
    for (size_t j = i; j < (size_t)N_*H_; j += st) { g_q[j]=0.f; g_k[j]=0.f; g_v[j]=0.f; g_o[j]=0.f; }
    for (size_t j = i; j < (size_t)N_*C_; j += st) out[j] = 0.f;
    if (i < E_) g_cnt[i] = 0;
}

// ---------------- sim-matrix column norms + sigmoid(gates) -----------------------
__global__ void prep_kernel(const float* __restrict__ sim, const float* __restrict__ gates) {
    int e = threadIdx.x >> 5, lane = threadIdx.x & 31;
    float s = 0.f;
    for (int c = lane; c < C_; c += 32) { float v = sim[(size_t)c*E_ + e]; s += v*v; }
    #pragma unroll
    for (int o = 16; o > 0; o >>= 1) s += __shfl_xor_sync(0xffffffffu, s, o);
    if (lane == 0) {
        g_invsn[e] = 1.0f / fmaxf(sqrtf(s), 1e-12f);
        g_sig[e]   = 1.0f / (1.0f + expf(-gates[e]));
    }
}

// ---------------- gating (one warp per token) ------------------------------------
__global__ void gating_kernel(const float* __restrict__ x, const float* __restrict__ sim) {
    int tok  = blockIdx.x * (blockDim.x >> 5) + (threadIdx.x >> 5);
    int lane = threadIdx.x & 31;
    if (tok >= N_) return;
    const float* xr = x + (size_t)tok * C_;

    float dot[E_];
    #pragma unroll
    for (int e = 0; e < E_; e++) dot[e] = 0.f;
    float nrm = 0.f;
    for (int c = lane; c < C_; c += 32) {
        float xv = xr[c];
        nrm += xv * xv;
        const float4* s4 = (const float4*)(sim + (size_t)c * E_);
        float4 r0 = s4[0], r1 = s4[1], r2 = s4[2], r3 = s4[3];
        dot[0]+=xv*r0.x; dot[1]+=xv*r0.y; dot[2]+=xv*r0.z; dot[3]+=xv*r0.w;
        dot[4]+=xv*r1.x; dot[5]+=xv*r1.y; dot[6]+=xv*r1.z; dot[7]+=xv*r1.w;
        dot[8]+=xv*r2.x; dot[9]+=xv*r2.y; dot[10]+=xv*r2.z; dot[11]+=xv*r2.w;
        dot[12]+=xv*r3.x; dot[13]+=xv*r3.y; dot[14]+=xv*r3.z; dot[15]+=xv*r3.w;
    }
    #pragma unroll
    for (int o = 16; o > 0; o >>= 1) {
        nrm += __shfl_xor_sync(0xffffffffu, nrm, o);
        #pragma unroll
        for (int e = 0; e < E_; e++) dot[e] += __shfl_xor_sync(0xffffffffu, dot[e], o);
    }
    float invx = 1.0f / fmaxf(sqrtf(nrm), 1e-12f);

    float logit[E_], gated[E_];
    unsigned msk = 0u;
    #pragma unroll
    for (int e = 0; e < E_; e++) {
        logit[e] = dot[e] * invx * g_invsn[e] - g_sig[e];
        gated[e] = fmaxf(logit[e], 0.f);
        if (logit[e] > 0.f) msk |= (1u << e);
    }
    if (msk == 0u) {
        float m1 = -3.4e38f; int i1 = 0;
        #pragma unroll
        for (int e = 0; e < E_; e++) if (logit[e] > m1) { m1 = logit[e]; i1 = e; }
        float m2 = -3.4e38f; int i2 = 0;
        #pragma unroll
        for (int e = 0; e < E_; e++) if (e != i1 && logit[e] > m2) { m2 = logit[e]; i2 = e; }
        msk = (1u << i1) | (1u << i2);
    }
    float mx = -3.4e38f;
    #pragma unroll
    for (int e = 0; e < E_; e++) if ((msk >> e) & 1u) mx = fmaxf(mx, gated[e]);
    float wv[E_]; float sum = 0.f;
    #pragma unroll
    for (int e = 0; e < E_; e++) {
        wv[e] = ((msk >> e) & 1u) ? expf(gated[e] - mx) : 0.f;
        sum += wv[e];
    }
    float inv = 1.0f / sum;
    #pragma unroll
    for (int e = 0; e < E_; e++) {
        if (lane == e && ((msk >> e) & 1u)) {
            int pos = atomicAdd(&g_cnt[e], 1);
            g_idx[(size_t)e * N_ + pos] = tok;
            g_wt [(size_t)e * N_ + pos] = wv[e] * inv;
        }
    }
}

// ---------------- f32 -> bf16 hi/lo split (vectorized) ---------------------------
__global__ void split2(const float* __restrict__ in, bf16* __restrict__ hi,
                       bf16* __restrict__ lo, long n4)
{
    long i  = (long)blockIdx.x * blockDim.x + threadIdx.x;
    long st = (long)gridDim.x * blockDim.x;
    for (; i < n4; i += st) {
        float4 v = ((const float4*)in)[i];
        bf16 h0 = __float2bfloat16(v.x), h1 = __float2bfloat16(v.y);
        bf16 h2 = __float2bfloat16(v.z), h3 = __float2bfloat16(v.w);
        bf162 hh0; hh0.x = h0; hh0.y = h1;
        bf162 hh1; hh1.x = h2; hh1.y = h3;
        ((bf162*)hi)[2*i]   = hh0;
        ((bf162*)hi)[2*i+1] = hh1;
        bf162 ll0, ll1;
        ll0.x = __float2bfloat16(v.x - __bfloat162float(h0));
        ll0.y = __float2bfloat16(v.y - __bfloat162float(h1));
        ll1.x = __float2bfloat16(v.z - __bfloat162float(h2));
        ll1.y = __float2bfloat16(v.w - __bfloat162float(h3));
        ((bf162*)lo)[2*i]   = ll0;
        ((bf162*)lo)[2*i+1] = ll1;
    }
}

// ---------------- transpose + split: out[c][r] = in[r][c] ------------------------
__global__ void tsplit(const float* __restrict__ in, bf16* __restrict__ oh,
                       bf16* __restrict__ ol, int R, int Cc)
{
    __shared__ float t[32][33];
    size_t zo = (size_t)blockIdx.z * R * Cc;
    in += zo; oh += zo; ol += zo;
    int c0 = blockIdx.x * 32, r0 = blockIdx.y * 32;
    int tx = threadIdx.x, ty = threadIdx.y;
    #pragma unroll
    for (int i = ty; i < 32; i += 8) t[i][tx] = in[(size_t)(r0 + i) * Cc + c0 + tx];
    __syncthreads();
    #pragma unroll
    for (int i = ty; i < 32; i += 8) {
        float v = t[tx][i];
        bf16 h = __float2bfloat16(v);
        size_t oidx = (size_t)(c0 + i) * R + r0 + tx;
        oh[oidx] = h;
        ol[oidx] = __float2bfloat16(v - __bfloat162float(h));
    }
}

// ---------------- softmax over S rows, writing bf16 hi/lo ------------------------
__global__ void softmax_split() {
    __shared__ float buf[T_];
    __shared__ float red[256];
    const float* S = g_S + (size_t)blockIdx.x * T_;
    bf16* sh = g_Sh + (size_t)blockIdx.x * T_;
    bf16* sl = g_Sl + (size_t)blockIdx.x * T_;
    int tid = threadIdx.x;
    float mx = -3.4e38f;
    for (int j = tid; j < T_; j += 256) { float v = S[j]; buf[j] = v; mx = fmaxf(mx, v); }
    red[tid] = mx; __syncthreads();
    for (int s = 128; s > 0; s >>= 1) { if (tid < s) red[tid] = fmaxf(red[tid], red[tid+s]); __syncthreads(); }
    mx = red[0];
    __syncthreads();
    float sum = 0.f;
    for (int j = tid; j < T_; j += 256) { float e = __expf(buf[j] - mx); buf[j] = e; sum += e; }
    red[tid] = sum; __syncthreads();
    for (int s = 128; s > 0; s >>= 1) { if (tid < s) red[tid] += red[tid+s]; __syncthreads(); }
    float inv = 1.0f / red[0];
    for (int j = tid; j < T_; j += 256) {
        float p = buf[j] * inv;
        bf16 h = __float2bfloat16(p);
        sh[j] = h;
        sl[j] = __float2bfloat16(p - __bfloat162float(h));
    }
}

// ---------------- launch ---------------------------------------------------------
extern "C" void kernel_launch(void* const* d_in, const int* in_sizes, int n_in,
                              void* d_out, int out_size)
{
    const float* x     = (const float*)d_in[0];
    const float* sim   = (const float*)d_in[1];
    const float* gates = (const float*)d_in[2];
    const float* qp    = (const float*)d_in[3];
    const float* kp    = (const float*)d_in[4];
    const float* vp    = (const float*)d_in[5];
    const float* op    = (const float*)d_in[6];
    float* outp = (float*)d_out;

    float *q, *k, *v, *o, *S, *wt;
    int *cnt, *idx;
    bf16 *xh, *xl, *qh, *ql, *kh, *kl, *vTh, *vTl, *oh, *ol, *Sh, *Sl;
    bf16 *wqh, *wql, *wkh, *wkl, *wvh, *wvl, *woh, *wol;
    cudaGetSymbolAddress((void**)&q, g_q);     cudaGetSymbolAddress((void**)&k, g_k);
    cudaGetSymbolAddress((void**)&v, g_v);     cudaGetSymbolAddress((void**)&o, g_o);
    cudaGetSymbolAddress((void**)&S, g_S);
    cudaGetSymbolAddress((void**)&cnt, g_cnt); cudaGetSymbolAddress((void**)&idx, g_idx);
    cudaGetSymbolAddress((void**)&wt, g_wt);
    cudaGetSymbolAddress((void**)&xh, g_xh);   cudaGetSymbolAddress((void**)&xl, g_xl);
    cudaGetSymbolAddress((void**)&qh, g_qh);   cudaGetSymbolAddress((void**)&ql, g_ql);
    cudaGetSymbolAddress((void**)&kh, g_kh);   cudaGetSymbolAddress((void**)&kl, g_kl);
    cudaGetSymbolAddress((void**)&vTh, g_vTh); cudaGetSymbolAddress((void**)&vTl, g_vTl);
    cudaGetSymbolAddress((void**)&oh, g_oh);   cudaGetSymbolAddress((void**)&ol, g_ol);
    cudaGetSymbolAddress((void**)&Sh, g_Sh);   cudaGetSymbolAddress((void**)&Sl, g_Sl);
    cudaGetSymbolAddress((void**)&wqh, g_wqh); cudaGetSymbolAddress((void**)&wql, g_wql);
    cudaGetSymbolAddress((void**)&wkh, g_wkh); cudaGetSymbolAddress((void**)&wkl, g_wkl);
    cudaGetSymbolAddress((void**)&wvh, g_wvh); cudaGetSymbolAddress((void**)&wvl, g_wvl);
    cudaGetSymbolAddress((void**)&woh, g_woh); cudaGetSymbolAddress((void**)&wol, g_wol);

    cudaFuncSetAttribute(hm_gemm<true,  true >, cudaFuncAttributeMaxDynamicSharedMemorySize, DSM_BYTES);
    cudaFuncSetAttribute(hm_gemm<false, false>, cudaFuncAttributeMaxDynamicSharedMemorySize, DSM_BYTES);
    cudaFuncSetAttribute(hm_gemm<false, true >, cudaFuncAttributeMaxDynamicSharedMemorySize, DSM_BYTES);

    zero_all<<<2048, 256>>>(outp);
    prep_kernel<<<1, 512>>>(sim, gates);
    gating_kernel<<<N_/8, 256>>>(x, sim);

    // pre-split / pre-transpose operands to bf16 hi/lo
    split2<<<2048, 256>>>(x, xh, xl, (long)N_*C_/4);
    tsplit<<<dim3(H_/32, C_/32, E_), dim3(32,8)>>>(qp, wqh, wql, C_, H_);   // [E][C][H]->[E][H][C]
    tsplit<<<dim3(H_/32, C_/32, E_), dim3(32,8)>>>(kp, wkh, wkl, C_, H_);
    tsplit<<<dim3(H_/32, C_/32, E_), dim3(32,8)>>>(vp, wvh, wvl, C_, H_);
    tsplit<<<dim3(C_/32, H_/32, E_), dim3(32,8)>>>(op, woh, wol, H_, C_);   // [E][H][C]->[E][C][H]

    // QKV MoE dispatch (gathered rows, weighted atomic accumulate into q/k/v f32)
    {
        TCArgs a{};
        a.Ah = xh; a.Al = xl;
        a.Bh0 = wqh; a.Bl0 = wql; a.Bh1 = wkh; a.Bl1 = wkl; a.Bh2 = wvh; a.Bl2 = wvl;
        a.C0 = q; a.C1 = k; a.C2 = v;
        a.sAz = 0; a.sBz = (long)H_*C_; a.sCz = 0;
        a.lda = C_; a.ldb = C_; a.ldc = H_;
        a.M = N_; a.K = C_; a.nxb = 1; a.nsplit = 1; a.ksplit = C_;
        a.alpha = 1.f; a.cnt = cnt; a.idxB = idx; a.wtB = wt;
        hm_gemm<true, true><<<dim3(3, 64, 16), 256, DSM_BYTES>>>(a);
    }

    split2<<<512, 256>>>(q, qh, ql, (long)N_*H_/4);
    split2<<<512, 256>>>(k, kh, kl, (long)N_*H_/4);
    tsplit<<<dim3(H_/32, T_/32, B_), dim3(32,8)>>>(v, vTh, vTl, T_, H_);    // [T][H]->[H][T] per batch

    // S = Q K^T / sqrt(H)
    {
        TCArgs a{};
        a.Ah = qh; a.Al = ql;
        a.Bh0 = kh; a.Bl0 = kl; a.Bh1 = kh; a.Bl1 = kl; a.Bh2 = kh; a.Bl2 = kl;
        a.C0 = S; a.C1 = S; a.C2 = S;
        a.sAz = (long)T_*H_; a.sBz = (long)T_*H_; a.sCz = (long)T_*T_;
        a.lda = H_; a.ldb = H_; a.ldc = T_;
        a.M = T_; a.K = H_; a.nxb = 16; a.nsplit = 1; a.ksplit = H_;
        a.alpha = 0.08838834764831845f;
        hm_gemm<false, false><<<dim3(16, 16, 4), 256, DSM_BYTES>>>(a);
    }

    softmax_split<<<B_*T_, 256>>>();

    // O = P V   (split-K x4, atomic accumulate into o f32)
    {
        TCArgs a{};
        a.Ah = Sh; a.Al = Sl;
        a.Bh0 = vTh; a.Bl0 = vTl; a.Bh1 = vTh; a.Bl1 = vTl; a.Bh2 = vTh; a.Bl2 = vTl;
        a.C0 = o; a.C1 = o; a.C2 = o;
        a.sAz = (long)T_*T_; a.sBz = (long)H_*T_; a.sCz = (long)T_*H_;
        a.lda = T_; a.ldb = T_; a.ldc = H_;
        a.M = T_; a.K = T_; a.nxb = 1; a.nsplit = 4; a.ksplit = 512;
        a.alpha = 1.f;
        hm_gemm<false, true><<<dim3(1, 16, 16), 256, DSM_BYTES>>>(a);
    }

    split2<<<512, 256>>>(o, oh, ol, (long)N_*H_/4);

    // output MoE combine (gathered rows, weighted atomic accumulate into out)
    {
        TCArgs a{};
        a.Ah = oh; a.Al = ol;
        a.Bh0 = woh; a.Bl0 = wol; a.Bh1 = woh; a.Bl1 = wol; a.Bh2 = woh; a.Bl2 = wol;
        a.C0 = outp; a.C1 = outp; a.C2 = outp;
        a.sAz = 0; a.sBz = (long)C_*H_; a.sCz = 0;
        a.lda = H_; a.ldb = H_; a.ldc = C_;
        a.M = N_; a.K = H_; a.nxb = 8; a.nsplit = 1; a.ksplit = H_;
        a.alpha = 1.f; a.cnt = cnt; a.idxB = idx; a.wtB = wt;
        hm_gemm<true, true><<<dim3(8, 64, 16), 256, DSM_BYTES>>>(a);
    }
}

// round 11
// speedup vs baseline: 3.6721x; 1.0826x over previous
#include <cuda_runtime.h>
#include <cuda_bf16.h>
#include <math.h>
#include <stdint.h>

#define B_ 4
#define T_ 2048
#define C_ 1024
#define H_ 128
#define E_ 16
#define N_ (B_*T_)   /* 8192 tokens */

using bf16  = __nv_bfloat16;
using bf162 = __nv_bfloat162;

// ---------------- scratch (allocation-free: __device__ globals) ----------------
__device__ float g_q[(size_t)N_*H_];
__device__ float g_k[(size_t)N_*H_];
__device__ float g_v[(size_t)N_*H_];
__device__ float g_o[(size_t)N_*H_];
__device__ float g_S[(size_t)B_*T_*T_];          // 64 MB f32 scores

__device__ bf16 g_xh[(size_t)N_*C_],  g_xl[(size_t)N_*C_];
__device__ bf16 g_qh[(size_t)N_*H_],  g_ql[(size_t)N_*H_];
__device__ bf16 g_kh[(size_t)N_*H_],  g_kl[(size_t)N_*H_];
__device__ bf16 g_vTh[(size_t)N_*H_], g_vTl[(size_t)N_*H_];   // [B][H][T]
__device__ bf16 g_oh[(size_t)N_*H_],  g_ol[(size_t)N_*H_];
__device__ bf16 g_Sh[(size_t)B_*T_*T_], g_Sl[(size_t)B_*T_*T_];
__device__ bf16 g_wqh[(size_t)E_*H_*C_], g_wql[(size_t)E_*H_*C_];  // [E][H][C]
__device__ bf16 g_wkh[(size_t)E_*H_*C_], g_wkl[(size_t)E_*H_*C_];
__device__ bf16 g_wvh[(size_t)E_*H_*C_], g_wvl[(size_t)E_*H_*C_];
__device__ bf16 g_woh[(size_t)E_*C_*H_], g_wol[(size_t)E_*C_*H_];  // [E][C][H]

__device__ int   g_cnt[E_];
__device__ int   g_idx[(size_t)E_*N_];
__device__ float g_wt[(size_t)E_*N_];
__device__ float g_invsn[E_];
__device__ float g_sig[E_];

// ---------------- mma.sync / ldmatrix / cp.async helpers (baseline PTX) ---------
#define MMA16816(d, A0, A1, A2, A3, Bv0, Bv1) \
    asm volatile("mma.sync.aligned.m16n8k16.row.col.f32.bf16.bf16.f32 " \
        "{%0,%1,%2,%3},{%4,%5,%6,%7},{%8,%9},{%0,%1,%2,%3};" \
        : "+f"((d)[0]), "+f"((d)[1]), "+f"((d)[2]), "+f"((d)[3]) \
        : "r"(A0), "r"(A1), "r"(A2), "r"(A3), "r"(Bv0), "r"(Bv1))

#define LDSM4(r0, r1, r2, r3, addr) \
    asm volatile("ldmatrix.sync.aligned.m8n8.x4.shared.b16 {%0,%1,%2,%3}, [%4];" \
        : "=r"(r0), "=r"(r1), "=r"(r2), "=r"(r3) : "r"(addr))

#define CPA16(dst, src) \
    asm volatile("cp.async.cg.shared.global [%0], [%1], 16;" :: "r"(dst), "l"(src))

__device__ __forceinline__ uint32_t smem_u32(const void* p) {
    uint32_t a;
    asm("{ .reg .u64 t; cvta.to.shared.u64 t, %1; cvt.u32.u64 %0, t; }" : "=r"(a) : "l"(p));
    return a;
}

// ---------------- HMMA GEMM -----------------------------------------------------
// D[m][n] = alpha * (w[m]) * sum_k A[m][k]*B[n][k]   (A,B split hi/lo bf16, K-major)
struct TCArgs {
    const bf16 *Ah, *Al;
    const bf16 *Bh0, *Bl0, *Bh1, *Bl1, *Bh2, *Bl2;
    float *C0, *C1, *C2;
    long sAz, sBz, sCz;
    int  lda, ldb, ldc;
    int  M, K, nxb, nsplit, ksplit;
    float alpha;
    const int* cnt; const int* idxB; const float* wtB;
};

#define PITCH 20   /* row pitch in b32 units: 16 b32 (32 bf16) + 4 pad */
#define TILE_U32 (128*PITCH)
#define DSM_BYTES (2*4*TILE_U32*4)   /* 2 buffers x 4 tiles = 81920 B */

template<bool GATHER, bool ATOMIC>
__global__ void __launch_bounds__(256, 2) hm_gemm(TCArgs a)
{
    int zb  = blockIdx.z / a.nsplit;
    int sp  = blockIdx.z % a.nsplit;
    int mat = blockIdx.x / a.nxb;
    int n0  = (blockIdx.x % a.nxb) * 128;

    int Mz = a.M;
    const int*   gidx = nullptr;
    const float* gwt  = nullptr;
    if (GATHER) {
        Mz   = a.cnt[zb];
        gidx = a.idxB + (size_t)zb * N_;
        gwt  = a.wtB  + (size_t)zb * N_;
    }
    int m0 = blockIdx.y * 128;
    if (m0 >= Mz) return;

    const bf16* Ah = a.Ah + (size_t)zb * a.sAz;
    const bf16* Al = a.Al + (size_t)zb * a.sAz;
    const bf16* Bh = (mat == 0 ? a.Bh0 : mat == 1 ? a.Bh1 : a.Bh2) + (size_t)zb * a.sBz;
    const bf16* Bl = (mat == 0 ? a.Bl0 : mat == 1 ? a.Bl1 : a.Bl2) + (size_t)zb * a.sBz;
    float*      C  = (mat == 0 ? a.C0  : mat == 1 ? a.C1  : a.C2)  + (size_t)zb * a.sCz;

    extern __shared__ uint32_t dsm[];
    uint32_t smbase = smem_u32(dsm);

    __shared__ int   s_idx[128];
    __shared__ float s_wt[128];

    int tid  = threadIdx.x;
    int lane = tid & 31, wid = tid >> 5;
    int g = lane >> 2, t = lane & 3;
    int wm = wid & 1, wn = wid >> 1;          // warp grid 2 (m) x 4 (n)
    int mbw = wm * 64, nbw = wn * 32;

    if (GATHER) {
        for (int i = tid; i < 128; i += 256) {
            int r = m0 + i;
            bool v = r < Mz;
            s_idx[i] = v ? gidx[r] : 0;
            s_wt[i]  = v ? gwt[r] : 0.f;
        }
    }
    __syncthreads();

    float acc[4][4][4];
    #pragma unroll
    for (int i = 0; i < 4; i++)
        #pragma unroll
        for (int j = 0; j < 4; j++)
            #pragma unroll
            for (int c = 0; c < 4; c++) acc[i][j][c] = 0.f;

    int kb = sp * a.ksplit;
    int ke = kb + a.ksplit; if (ke > a.K) ke = a.K;
    int nch = (ke - kb) >> 5;

    // per-thread global load coordinates (fixed across k-chunks)
    int f0row = tid >> 2,          f0kq = tid & 3;
    int f1row = (tid + 256) >> 2,  f1kq = (tid + 256) & 3;
    long ar0 = GATHER ? (long)s_idx[f0row] : (long)(m0 + f0row);
    long ar1 = GATHER ? (long)s_idx[f1row] : (long)(m0 + f1row);
    long br0 = (long)(n0 + f0row), br1 = (long)(n0 + f1row);
    uint32_t so0 = (uint32_t)(f0row * PITCH + f0kq * 4) * 4u;
    uint32_t so1 = (uint32_t)(f1row * PITCH + f1kq * 4) * 4u;

    // ldmatrix lane-address offsets (bytes)
    int jj = lane >> 3, rr = lane & 7;
    uint32_t aoff = (uint32_t)(((jj & 1) * 8 + rr) * PITCH + (jj >> 1) * 4) * 4u;
    uint32_t boff = (uint32_t)(((jj >> 1) * 8 + rr) * PITCH + (jj & 1) * 4) * 4u;
    uint32_t baseA = smbase + (uint32_t)(mbw * PITCH) * 4u + aoff;   // + tile offsets below
    uint32_t baseB = smbase + (uint32_t)(nbw * PITCH) * 4u + boff;
    const uint32_t TB = (uint32_t)TILE_U32 * 4u;   // tile stride in bytes

    // chunk loader: 8 cp.async of 16B into buffer b
    auto load_chunk = [&](int k0, int b) {
        uint32_t bb = (uint32_t)(b * 4) * TB;
        CPA16(smbase + bb + 0*TB + so0, Ah + ar0 * (long)a.lda + k0 + f0kq * 8);
        CPA16(smbase + bb + 1*TB + so0, Al + ar0 * (long)a.lda + k0 + f0kq * 8);
        CPA16(smbase + bb + 2*TB + so0, Bh + br0 * (long)a.ldb + k0 + f0kq * 8);
        CPA16(smbase + bb + 3*TB + so0, Bl + br0 * (long)a.ldb + k0 + f0kq * 8);
        CPA16(smbase + bb + 0*TB + so1, Ah + ar1 * (long)a.lda + k0 + f1kq * 8);
        CPA16(smbase + bb + 1*TB + so1, Al + ar1 * (long)a.lda + k0 + f1kq * 8);
        CPA16(smbase + bb + 2*TB + so1, Bh + br1 * (long)a.ldb + k0 + f1kq * 8);
        CPA16(smbase + bb + 3*TB + so1, Bl + br1 * (long)a.ldb + k0 + f1kq * 8);
    };

    load_chunk(kb, 0);
    asm volatile("cp.async.commit_group;" ::: "memory");

    for (int i = 0; i < nch; i++) {
        if (i + 1 < nch) {
            load_chunk(kb + (i + 1) * 32, (i + 1) & 1);
            asm volatile("cp.async.commit_group;" ::: "memory");
            asm volatile("cp.async.wait_group 1;" ::: "memory");
        } else {
            asm volatile("cp.async.wait_group 0;" ::: "memory");
        }
        __syncthreads();

        uint32_t bb = (uint32_t)((i & 1) * 4) * TB;
        uint32_t bAh = baseA + bb + 0*TB, bAl = baseA + bb + 1*TB;
        uint32_t bBh = baseB + bb + 2*TB, bBl = baseB + bb + 3*TB;

        #pragma unroll
        for (int kk = 0; kk < 2; kk++) {
            uint32_t kadd = (uint32_t)(kk * 8) * 4u;
            uint32_t bh[4][2], bl[4][2];
            #pragma unroll
            for (int np = 0; np < 2; np++) {
                uint32_t ba = (uint32_t)(np * 16 * PITCH) * 4u + kadd;
                LDSM4(bh[2*np][0], bh[2*np][1], bh[2*np+1][0], bh[2*np+1][1], bBh + ba);
                LDSM4(bl[2*np][0], bl[2*np][1], bl[2*np+1][0], bl[2*np+1][1], bBl + ba);
            }
            #pragma unroll
            for (int mt = 0; mt < 4; mt++) {
                uint32_t ma = (uint32_t)(mt * 16 * PITCH) * 4u + kadd;
                uint32_t ah0, ah1, ah2, ah3, al0, al1, al2, al3;
                LDSM4(ah0, ah1, ah2, ah3, bAh + ma);
                LDSM4(al0, al1, al2, al3, bAl + ma);
                #pragma unroll
                for (int nt = 0; nt < 4; nt++) {
                    MMA16816(acc[mt][nt], ah0, ah1, ah2, ah3, bh[nt][0], bh[nt][1]);
                    MMA16816(acc[mt][nt], ah0, ah1, ah2, ah3, bl[nt][0], bl[nt][1]);
                    MMA16816(acc[mt][nt], al0, al1, al2, al3, bh[nt][0], bh[nt][1]);
                }
            }
        }
        __syncthreads();
    }

    // epilogue: c0,c1 -> row (g), cols 2t,2t+1 ; c2,c3 -> row (g+8)
    #pragma unroll
    for (int mt = 0; mt < 4; mt++) {
        #pragma unroll
        for (int half = 0; half < 2; half++) {
            int lr = mbw + mt * 16 + g + half * 8;
            bool rv; long orow; float sc;
            if (GATHER) { rv = (m0 + lr) < Mz; orow = s_idx[lr]; sc = a.alpha * s_wt[lr]; }
            else        { rv = true;           orow = m0 + lr;   sc = a.alpha; }
            if (rv) {
                float* cp = C + orow * (long)a.ldc + n0 + nbw;
                #pragma unroll
                for (int nt = 0; nt < 4; nt++) {
                    int col = nt * 8 + 2 * t;
                    float v0 = acc[mt][nt][half * 2 + 0] * sc;
                    float v1 = acc[mt][nt][half * 2 + 1] * sc;
                    if (ATOMIC) { atomicAdd(cp + col, v0); atomicAdd(cp + col + 1, v1); }
                    else        { float2 vv; vv.x = v0; vv.y = v1; *(float2*)(cp + col) = vv; }
                }
            }
        }
    }
}

// ---------------- zero init (vectorized) -----------------------------------------
__global__ void zero_all(float* __restrict__ out) {
    size_t i  = (size_t)blockIdx.x * blockDim.x + threadIdx.x;
    size_t st = (size_t)gridDim.x * blockDim.x;
    float4 z = make_float4(0.f, 0.f, 0.f, 0.f);
    size_t nqkv = (size_t)N_*H_/4;
    for (size_t j = i; j < nqkv; j += st) {
        ((float4*)g_q)[j] = z; ((float4*)g_k)[j] = z;
        ((float4*)g_v)[j] = z; ((float4*)g_o)[j] = z;
    }
    size_t nout = (size_t)N_*C_/4;
    for (size_t j = i; j < nout; j += st) ((float4*)out)[j] = z;
    if (i < E_) g_cnt[i] = 0;
}

// ---------------- sim-matrix column norms + sigmoid(gates) -----------------------
__global__ void prep_kernel(const float* __restrict__ sim, const float* __restrict__ gates) {
    int e = threadIdx.x >> 5, lane = threadIdx.x & 31;
    float s = 0.f;
    for (int c = lane; c < C_; c += 32) { float v = sim[(size_t)c*E_ + e]; s += v*v; }
    #pragma unroll
    for (int o = 16; o > 0; o >>= 1) s += __shfl_xor_sync(0xffffffffu, s, o);
    if (lane == 0) {
        g_invsn[e] = 1.0f / fmaxf(sqrtf(s), 1e-12f);
        g_sig[e]   = 1.0f / (1.0f + expf(-gates[e]));
    }
}

// ---------------- gating (one warp per token) ------------------------------------
__global__ void gating_kernel(const float* __restrict__ x, const float* __restrict__ sim) {
    int tok  = blockIdx.x * (blockDim.x >> 5) + (threadIdx.x >> 5);
    int lane = threadIdx.x & 31;
    if (tok >= N_) return;
    const float* xr = x + (size_t)tok * C_;

    float dot[E_];
    #pragma unroll
    for (int e = 0; e < E_; e++) dot[e] = 0.f;
    float nrm = 0.f;
    for (int c = lane; c < C_; c += 32) {
        float xv = xr[c];
        nrm += xv * xv;
        const float4* s4 = (const float4*)(sim + (size_t)c * E_);
        float4 r0 = s4[0], r1 = s4[1], r2 = s4[2], r3 = s4[3];
        dot[0]+=xv*r0.x; dot[1]+=xv*r0.y; dot[2]+=xv*r0.z; dot[3]+=xv*r0.w;
        dot[4]+=xv*r1.x; dot[5]+=xv*r1.y; dot[6]+=xv*r1.z; dot[7]+=xv*r1.w;
        dot[8]+=xv*r2.x; dot[9]+=xv*r2.y; dot[10]+=xv*r2.z; dot[11]+=xv*r2.w;
        dot[12]+=xv*r3.x; dot[13]+=xv*r3.y; dot[14]+=xv*r3.z; dot[15]+=xv*r3.w;
    }
    #pragma unroll
    for (int o = 16; o > 0; o >>= 1) {
        nrm += __shfl_xor_sync(0xffffffffu, nrm, o);
        #pragma unroll
        for (int e = 0; e < E_; e++) dot[e] += __shfl_xor_sync(0xffffffffu, dot[e], o);
    }
    float invx = 1.0f / fmaxf(sqrtf(nrm), 1e-12f);

    float logit[E_], gated[E_];
    unsigned msk = 0u;
    #pragma unroll
    for (int e = 0; e < E_; e++) {
        logit[e] = dot[e] * invx * g_invsn[e] - g_sig[e];
        gated[e] = fmaxf(logit[e], 0.f);
        if (logit[e] > 0.f) msk |= (1u << e);
    }
    if (msk == 0u) {
        float m1 = -3.4e38f; int i1 = 0;
        #pragma unroll
        for (int e = 0; e < E_; e++) if (logit[e] > m1) { m1 = logit[e]; i1 = e; }
        float m2 = -3.4e38f; int i2 = 0;
        #pragma unroll
        for (int e = 0; e < E_; e++) if (e != i1 && logit[e] > m2) { m2 = logit[e]; i2 = e; }
        msk = (1u << i1) | (1u << i2);
    }
    float mx = -3.4e38f;
    #pragma unroll
    for (int e = 0; e < E_; e++) if ((msk >> e) & 1u) mx = fmaxf(mx, gated[e]);
    float wv[E_]; float sum = 0.f;
    #pragma unroll
    for (int e = 0; e < E_; e++) {
        wv[e] = ((msk >> e) & 1u) ? expf(gated[e] - mx) : 0.f;
        sum += wv[e];
    }
    float inv = 1.0f / sum;
    #pragma unroll
    for (int e = 0; e < E_; e++) {
        if (lane == e && ((msk >> e) & 1u)) {
            int pos = atomicAdd(&g_cnt[e], 1);
            g_idx[(size_t)e * N_ + pos] = tok;
            g_wt [(size_t)e * N_ + pos] = wv[e] * inv;
        }
    }
}

// ---------------- f32 -> bf16 hi/lo split (vectorized) ---------------------------
__global__ void split2(const float* __restrict__ in, bf16* __restrict__ hi,
                       bf16* __restrict__ lo, long n4)
{
    long i  = (long)blockIdx.x * blockDim.x + threadIdx.x;
    long st = (long)gridDim.x * blockDim.x;
    for (; i < n4; i += st) {
        float4 v = ((const float4*)in)[i];
        bf16 h0 = __float2bfloat16(v.x), h1 = __float2bfloat16(v.y);
        bf16 h2 = __float2bfloat16(v.z), h3 = __float2bfloat16(v.w);
        bf162 hh0; hh0.x = h0; hh0.y = h1;
        bf162 hh1; hh1.x = h2; hh1.y = h3;
        ((bf162*)hi)[2*i]   = hh0;
        ((bf162*)hi)[2*i+1] = hh1;
        bf162 ll0, ll1;
        ll0.x = __float2bfloat16(v.x - __bfloat162float(h0));
        ll0.y = __float2bfloat16(v.y - __bfloat162float(h1));
        ll1.x = __float2bfloat16(v.z - __bfloat162float(h2));
        ll1.y = __float2bfloat16(v.w - __bfloat162float(h3));
        ((bf162*)lo)[2*i]   = ll0;
        ((bf162*)lo)[2*i+1] = ll1;
    }
}

// ---------------- transpose + split: out[c][r] = in[r][c] ------------------------
__global__ void tsplit(const float* __restrict__ in, bf16* __restrict__ oh,
                       bf16* __restrict__ ol, int R, int Cc)
{
    __shared__ float t[32][33];
    size_t zo = (size_t)blockIdx.z * R * Cc;
    in += zo; oh += zo; ol += zo;
    int c0 = blockIdx.x * 32, r0 = blockIdx.y * 32;
    int tx = threadIdx.x, ty = threadIdx.y;
    #pragma unroll
    for (int i = ty; i < 32; i += 8) t[i][tx] = in[(size_t)(r0 + i) * Cc + c0 + tx];
    __syncthreads();
    #pragma unroll
    for (int i = ty; i < 32; i += 8) {
        float v = t[tx][i];
        bf16 h = __float2bfloat16(v);
        size_t oidx = (size_t)(c0 + i) * R + r0 + tx;
        oh[oidx] = h;
        ol[oidx] = __float2bfloat16(v - __bfloat162float(h));
    }
}

// ---------------- merged weight transpose+split (all 4 proj matrices) ------------
// z = e*4 + mat; mat 0..2: [E][C][H] -> [E][H][C]; mat 3: [E][H][C] -> [E][C][H]
__global__ void tsplit_all(const float* __restrict__ qp, const float* __restrict__ kp,
                           const float* __restrict__ vp, const float* __restrict__ op)
{
    __shared__ float t[32][33];
    int z = blockIdx.z;
    int e = z >> 2, mat = z & 3;
    const float* in;
    bf16 *oh, *ol;
    int R, Cc, c0, r0;
    if (mat == 0)      { in = qp; oh = g_wqh; ol = g_wql; }
    else if (mat == 1) { in = kp; oh = g_wkh; ol = g_wkl; }
    else if (mat == 2) { in = vp; oh = g_wvh; ol = g_wvl; }
    else               { in = op; oh = g_woh; ol = g_wol; }
    if (mat < 3) { R = C_; Cc = H_; c0 = blockIdx.x * 32; r0 = blockIdx.y * 32; }
    else         { R = H_; Cc = C_; c0 = blockIdx.y * 32; r0 = blockIdx.x * 32; }
    size_t zo = (size_t)e * R * Cc;
    in += zo; oh += zo; ol += zo;
    int tx = threadIdx.x, ty = threadIdx.y;
    #pragma unroll
    for (int i = ty; i < 32; i += 8) t[i][tx] = in[(size_t)(r0 + i) * Cc + c0 + tx];
    __syncthreads();
    #pragma unroll
    for (int i = ty; i < 32; i += 8) {
        float v = t[tx][i];
        bf16 h = __float2bfloat16(v);
        size_t oidx = (size_t)(c0 + i) * R + r0 + tx;
        oh[oidx] = h;
        ol[oidx] = __float2bfloat16(v - __bfloat162float(h));
    }
}

// ---------------- softmax over S rows, writing bf16 hi/lo (vectorized) -----------
__global__ void softmax_split() {
    __shared__ float buf[T_];
    __shared__ float red[8];
    const float4* S4 = (const float4*)(g_S + (size_t)blockIdx.x * T_);
    bf162* sh = (bf162*)(g_Sh + (size_t)blockIdx.x * T_);
    bf162* sl = (bf162*)(g_Sl + (size_t)blockIdx.x * T_);
    int tid = threadIdx.x, lane = tid & 31, wrp = tid >> 5;

    float mx = -3.4e38f;
    #pragma unroll
    for (int it = 0; it < 2; it++) {
        int j = tid + it * 256;
        float4 v = S4[j];
        ((float4*)buf)[j] = v;
        mx = fmaxf(mx, fmaxf(fmaxf(v.x, v.y), fmaxf(v.z, v.w)));
    }
    #pragma unroll
    for (int o = 16; o > 0; o >>= 1) mx = fmaxf(mx, __shfl_xor_sync(0xffffffffu, mx, o));
    if (lane == 0) red[wrp] = mx;
    __syncthreads();
    mx = red[lane & 7];
    #pragma unroll
    for (int o = 4; o > 0; o >>= 1) mx = fmaxf(mx, __shfl_xor_sync(0xffffffffu, mx, o));

    float sum = 0.f;
    #pragma unroll
    for (int it = 0; it < 2; it++) {
        int j = tid + it * 256;
        float4 v = ((float4*)buf)[j];
        v.x = __expf(v.x - mx); v.y = __expf(v.y - mx);
        v.z = __expf(v.z - mx); v.w = __expf(v.w - mx);
        ((float4*)buf)[j] = v;
        sum += v.x + v.y + v.z + v.w;
    }
    #pragma unroll
    for (int o = 16; o > 0; o >>= 1) sum += __shfl_xor_sync(0xffffffffu, sum, o);
    __syncthreads();
    if (lane == 0) red[wrp] = sum;
    __syncthreads();
    sum = red[lane & 7];
    #pragma unroll
    for (int o = 4; o > 0; o >>= 1) sum += __shfl_xor_sync(0xffffffffu, sum, o);
    float inv = 1.0f / sum;

    #pragma unroll
    for (int it = 0; it < 2; it++) {
        int j = tid + it * 256;
        float4 v = ((float4*)buf)[j];
        float p0 = v.x * inv, p1 = v.y * inv, p2 = v.z * inv, p3 = v.w * inv;
        bf16 h0 = __float2bfloat16(p0), h1 = __float2bfloat16(p1);
        bf16 h2 = __float2bfloat16(p2), h3 = __float2bfloat16(p3);
        bf162 hh0; hh0.x = h0; hh0.y = h1;
        bf162 hh1; hh1.x = h2; hh1.y = h3;
        sh[2*j] = hh0; sh[2*j+1] = hh1;
        bf162 ll0, ll1;
        ll0.x = __float2bfloat16(p0 - __bfloat162float(h0));
        ll0.y = __float2bfloat16(p1 - __bfloat162float(h1));
        ll1.x = __float2bfloat16(p2 - __bfloat162float(h2));
        ll1.y = __float2bfloat16(p3 - __bfloat162float(h3));
        sl[2*j] = ll0; sl[2*j+1] = ll1;
    }
}

// ---------------- launch ---------------------------------------------------------
extern "C" void kernel_launch(void* const* d_in, const int* in_sizes, int n_in,
                              void* d_out, int out_size)
{
    const float* x     = (const float*)d_in[0];
    const float* sim   = (const float*)d_in[1];
    const float* gates = (const float*)d_in[2];
    const float* qp    = (const float*)d_in[3];
    const float* kp    = (const float*)d_in[4];
    const float* vp    = (const float*)d_in[5];
    const float* op    = (const float*)d_in[6];
    float* outp = (float*)d_out;

    float *q, *k, *v, *o, *S, *wt;
    int *cnt, *idx;
    bf16 *xh, *xl, *qh, *ql, *kh, *kl, *vTh, *vTl, *oh, *ol, *Sh, *Sl;
    bf16 *wqh, *wql, *wkh, *wkl, *wvh, *wvl, *woh, *wol;
    cudaGetSymbolAddress((void**)&q, g_q);     cudaGetSymbolAddress((void**)&k, g_k);
    cudaGetSymbolAddress((void**)&v, g_v);     cudaGetSymbolAddress((void**)&o, g_o);
    cudaGetSymbolAddress((void**)&S, g_S);
    cudaGetSymbolAddress((void**)&cnt, g_cnt); cudaGetSymbolAddress((void**)&idx, g_idx);
    cudaGetSymbolAddress((void**)&wt, g_wt);
    cudaGetSymbolAddress((void**)&xh, g_xh);   cudaGetSymbolAddress((void**)&xl, g_xl);
    cudaGetSymbolAddress((void**)&qh, g_qh);   cudaGetSymbolAddress((void**)&ql, g_ql);
    cudaGetSymbolAddress((void**)&kh, g_kh);   cudaGetSymbolAddress((void**)&kl, g_kl);
    cudaGetSymbolAddress((void**)&vTh, g_vTh); cudaGetSymbolAddress((void**)&vTl, g_vTl);
    cudaGetSymbolAddress((void**)&oh, g_oh);   cudaGetSymbolAddress((void**)&ol, g_ol);
    cudaGetSymbolAddress((void**)&Sh, g_Sh);   cudaGetSymbolAddress((void**)&Sl, g_Sl);
    cudaGetSymbolAddress((void**)&wqh, g_wqh); cudaGetSymbolAddress((void**)&wql, g_wql);
    cudaGetSymbolAddress((void**)&wkh, g_wkh); cudaGetSymbolAddress((void**)&wkl, g_wkl);
    cudaGetSymbolAddress((void**)&wvh, g_wvh); cudaGetSymbolAddress((void**)&wvl, g_wvl);
    cudaGetSymbolAddress((void**)&woh, g_woh); cudaGetSymbolAddress((void**)&wol, g_wol);

    cudaFuncSetAttribute(hm_gemm<true,  true >, cudaFuncAttributeMaxDynamicSharedMemorySize, DSM_BYTES);
    cudaFuncSetAttribute(hm_gemm<false, false>, cudaFuncAttributeMaxDynamicSharedMemorySize, DSM_BYTES);
    cudaFuncSetAttribute(hm_gemm<false, true >, cudaFuncAttributeMaxDynamicSharedMemorySize, DSM_BYTES);

    // launch order arranged so the QKV HMMA GEMM is launch #6 (ncu -s 5 -c 1)
    zero_all<<<2048, 256>>>(outp);                                   // 1
    prep_kernel<<<1, 512>>>(sim, gates);                             // 2
    gating_kernel<<<N_/8, 256>>>(x, sim);                            // 3
    tsplit_all<<<dim3(4, 32, E_*4), dim3(32,8)>>>(qp, kp, vp, op);   // 4
    split2<<<2048, 256>>>(x, xh, xl, (long)N_*C_/4);                 // 5

    // 6: QKV MoE dispatch (gathered rows, weighted atomic accumulate into q/k/v f32)
    {
        TCArgs a{};
        a.Ah = xh; a.Al = xl;
        a.Bh0 = wqh; a.Bl0 = wql; a.Bh1 = wkh; a.Bl1 = wkl; a.Bh2 = wvh; a.Bl2 = wvl;
        a.C0 = q; a.C1 = k; a.C2 = v;
        a.sAz = 0; a.sBz = (long)H_*C_; a.sCz = 0;
        a.lda = C_; a.ldb = C_; a.ldc = H_;
        a.M = N_; a.K = C_; a.nxb = 1; a.nsplit = 1; a.ksplit = C_;
        a.alpha = 1.f; a.cnt = cnt; a.idxB = idx; a.wtB = wt;
        hm_gemm<true, true><<<dim3(3, 64, 16), 256, DSM_BYTES>>>(a);
    }

    split2<<<512, 256>>>(q, qh, ql, (long)N_*H_/4);
    split2<<<512, 256>>>(k, kh, kl, (long)N_*H_/4);
    tsplit<<<dim3(H_/32, T_/32, B_), dim3(32,8)>>>(v, vTh, vTl, T_, H_);    // [T][H]->[H][T] per batch

    // S = Q K^T / sqrt(H)
    {
        TCArgs a{};
        a.Ah = qh; a.Al = ql;
        a.Bh0 = kh; a.Bl0 = kl; a.Bh1 = kh; a.Bl1 = kl; a.Bh2 = kh; a.Bl2 = kl;
        a.C0 = S; a.C1 = S; a.C2 = S;
        a.sAz = (long)T_*H_; a.sBz = (long)T_*H_; a.sCz = (long)T_*T_;
        a.lda = H_; a.ldb = H_; a.ldc = T_;
        a.M = T_; a.K = H_; a.nxb = 16; a.nsplit = 1; a.ksplit = H_;
        a.alpha = 0.08838834764831845f;
        hm_gemm<false, false><<<dim3(16, 16, 4), 256, DSM_BYTES>>>(a);
    }

    softmax_split<<<B_*T_, 256>>>();

    // O = P V   (split-K x4, atomic accumulate into o f32)
    {
        TCArgs a{};
        a.Ah = Sh; a.Al = Sl;
        a.Bh0 = vTh; a.Bl0 = vTl; a.Bh1 = vTh; a.Bl1 = vTl; a.Bh2 = vTh; a.Bl2 = vTl;
        a.C0 = o; a.C1 = o; a.C2 = o;
        a.sAz = (long)T_*T_; a.sBz = (long)H_*T_; a.sCz = (long)T_*H_;
        a.lda = T_; a.ldb = T_; a.ldc = H_;
        a.M = T_; a.K = T_; a.nxb = 1; a.nsplit = 4; a.ksplit = 512;
        a.alpha = 1.f;
        hm_gemm<false, true><<<dim3(1, 16, 16), 256, DSM_BYTES>>>(a);
    }

    split2<<<512, 256>>>(o, oh, ol, (long)N_*H_/4);

    // output MoE combine (gathered rows, weighted atomic accumulate into out)
    {
        TCArgs a{};
        a.Ah = oh; a.Al = ol;
        a.Bh0 = woh; a.Bl0 = wol; a.Bh1 = woh; a.Bl1 = wol; a.Bh2 = woh; a.Bl2 = wol;
        a.C0 = outp; a.C1 = outp; a.C2 = outp;
        a.sAz = 0; a.sBz = (long)C_*H_; a.sCz = 0;
        a.lda = H_; a.ldb = H_; a.ldc = C_;
        a.M = N_; a.K = H_; a.nxb = 8; a.nsplit = 1; a.ksplit = H_;
        a.alpha = 1.f; a.cnt = cnt; a.idxB = idx; a.wtB = wt;
        hm_gemm<true, true><<<dim3(8, 64, 16), 256, DSM_BYTES>>>(a);
    }
}